// round 2
// baseline (speedup 1.0000x reference)
#include <cuda_runtime.h>

// ---------------------------------------------------------------------------
// GIN layer: out = BN( relu( ((1+eps)x + scatter_sum(x[src] -> dst)) @ W1 + b1 ) @ W2 + b2 )
// N = 100000, D = 256, E = 1600000
// ---------------------------------------------------------------------------

#define NNODE 100000
#define DIM   256
#define DIM2  512

constexpr int NB_STAT = 1184;   // BN partial-reduction blocks (8 per SM)

// Scratch (allocation-free: __device__ globals)
__device__ float g_agg[(long long)NNODE * DIM];    // (1+eps)*x + neigh
__device__ float g_h1 [(long long)NNODE * DIM2];   // relu(h @ W1 + b1)
__device__ float g_h2 [(long long)NNODE * DIM];    // h1 @ W2 + b2
__device__ float g_part[NB_STAT * 512];            // BN partials: [blk][sum256|sumsq256]
__device__ float g_mean[DIM];
__device__ float g_istd[DIM];
__device__ int   g_idx64;                          // 1 if src/dst are int64, 0 if int32

// ---------------------------------------------------------------------------
// Index-dtype detection: int64 values < 2^31 have zero high words.
// Sample 64 odd 32-bit words; all zero => int64 (P(false positive) ~ 1e-320).
// ---------------------------------------------------------------------------
__global__ void detect_idx_kernel(const int* __restrict__ words) {
    int allzero = 1;
    for (int i = 1; i < 129; i += 2) {
        if (words[i] != 0) { allzero = 0; break; }
    }
    g_idx64 = allzero;
}

__device__ __forceinline__ long long load_idx(const void* p, long long i) {
    if (g_idx64) return ((const long long*)p)[i];
    return (long long)((const int*)p)[i];
}

// ---------------------------------------------------------------------------
// 1) g_agg = (1 + eps) * x            (seeds the scatter accumulator)
// ---------------------------------------------------------------------------
__global__ void init_agg_kernel(const float* __restrict__ x,
                                const float* __restrict__ eps,
                                long long nq4) {
    const float s = 1.0f + eps[0];
    long long t = (long long)blockIdx.x * blockDim.x + threadIdx.x;
    if (t >= nq4) return;
    float4 v = ((const float4*)x)[t];
    v.x *= s; v.y *= s; v.z *= s; v.w *= s;
    ((float4*)g_agg)[t] = v;
}

// ---------------------------------------------------------------------------
// 2) scatter: g_agg[dst[e]] += x[src[e]]   (vectorized fp32 red.global.add.v4)
//    64 consecutive threads handle one edge (64 x float4 = 256 floats).
// ---------------------------------------------------------------------------
__global__ void scatter_kernel(const float* __restrict__ x,
                               const void* __restrict__ src,
                               const void* __restrict__ dst,
                               long long nedges) {
    long long t = (long long)blockIdx.x * blockDim.x + threadIdx.x;
    long long total = nedges * 64;
    if (t >= total) return;
    long long e = t >> 6;
    int       c = (int)(t & 63);

    long long s = load_idx(src, e);
    long long d = load_idx(dst, e);

    float4 v = ((const float4*)(x + s * DIM))[c];
    float* addr = g_agg + d * DIM + (long long)c * 4;
    asm volatile("red.global.add.v4.f32 [%0], {%1,%2,%3,%4};"
                 :: "l"(addr), "f"(v.x), "f"(v.y), "f"(v.z), "f"(v.w)
                 : "memory");
}

// ---------------------------------------------------------------------------
// 3) SGEMM: C[M,Ncols] = A[M,K] @ B[K,Ncols] + bias (+ optional ReLU)
//    128x128 tile, BK=16, 256 threads, 8x8 micro-tile per thread.
// ---------------------------------------------------------------------------
__global__ __launch_bounds__(256, 2)
void sgemm_kernel(const float* __restrict__ A, const float* __restrict__ B,
                  const float* __restrict__ bias, float* __restrict__ C,
                  int M, int K, int Ncols, int do_relu) {
    __shared__ float As[16][128];
    __shared__ float Bs[16][128];

    const int tid = threadIdx.x;
    const int tx = tid & 15;       // column group  (8 cols each)
    const int ty = tid >> 4;       // row group     (8 rows each)
    const int m0 = blockIdx.y * 128;
    const int n0 = blockIdx.x * 128;

    float acc[8][8];
#pragma unroll
    for (int i = 0; i < 8; i++)
#pragma unroll
        for (int j = 0; j < 8; j++) acc[i][j] = 0.0f;

    for (int k0 = 0; k0 < K; k0 += 16) {
        // Load A tile (128 rows x 16 cols), store transposed As[k][row]
#pragma unroll
        for (int l = 0; l < 2; l++) {
            int i  = tid + l * 256;          // 0..511 float4 slots
            int r  = i >> 2;                 // 0..127
            int kc = i & 3;                  // 0..3  (float4 along K)
            float4 av = make_float4(0.f, 0.f, 0.f, 0.f);
            if (m0 + r < M)
                av = *(const float4*)(A + (long long)(m0 + r) * K + k0 + kc * 4);
            As[kc * 4 + 0][r] = av.x;
            As[kc * 4 + 1][r] = av.y;
            As[kc * 4 + 2][r] = av.z;
            As[kc * 4 + 3][r] = av.w;
        }
        // Load B tile (16 rows x 128 cols), direct
#pragma unroll
        for (int l = 0; l < 2; l++) {
            int i  = tid + l * 256;
            int r  = i >> 5;                 // 0..15
            int c4 = i & 31;                 // 0..31
            float4 bv = *(const float4*)(B + (long long)(k0 + r) * Ncols + n0 + c4 * 4);
            ((float4*)&Bs[r][0])[c4] = bv;
        }
        __syncthreads();

#pragma unroll
        for (int k = 0; k < 16; k++) {
            float a[8], b[8];
            *(float4*)&a[0] = *(float4*)&As[k][ty * 8];
            *(float4*)&a[4] = *(float4*)&As[k][ty * 8 + 4];
            *(float4*)&b[0] = *(float4*)&Bs[k][tx * 8];
            *(float4*)&b[4] = *(float4*)&Bs[k][tx * 8 + 4];
#pragma unroll
            for (int i = 0; i < 8; i++)
#pragma unroll
                for (int j = 0; j < 8; j++)
                    acc[i][j] = fmaf(a[i], b[j], acc[i][j]);
        }
        __syncthreads();
    }

    // Epilogue: bias (+ReLU), guarded store
#pragma unroll
    for (int i = 0; i < 8; i++) {
        int row = m0 + ty * 8 + i;
        if (row >= M) continue;
#pragma unroll
        for (int j = 0; j < 8; j += 4) {
            int col = n0 + tx * 8 + j;
            float4 bv = *(const float4*)(bias + col);
            float4 v;
            v.x = acc[i][j + 0] + bv.x;
            v.y = acc[i][j + 1] + bv.y;
            v.z = acc[i][j + 2] + bv.z;
            v.w = acc[i][j + 3] + bv.w;
            if (do_relu) {
                v.x = fmaxf(v.x, 0.f); v.y = fmaxf(v.y, 0.f);
                v.z = fmaxf(v.z, 0.f); v.w = fmaxf(v.w, 0.f);
            }
            *(float4*)(C + (long long)row * Ncols + col) = v;
        }
    }
}

// ---------------------------------------------------------------------------
// 4) BN: column-wise partial sums/sumsq over g_h2 [N, 256]
// ---------------------------------------------------------------------------
__global__ void bn_partial_kernel(long long n) {
    int tid = threadIdx.x;    // 256 threads, one column each
    float s = 0.f, q = 0.f;
    for (long long r = blockIdx.x; r < n; r += gridDim.x) {
        float v = g_h2[r * DIM + tid];
        s += v;
        q += v * v;
    }
    g_part[blockIdx.x * 512 + tid]       = s;
    g_part[blockIdx.x * 512 + 256 + tid] = q;
}

__global__ void bn_finalize_kernel(float invN) {
    int tid = threadIdx.x;    // 256 threads
    float s = 0.f, q = 0.f;
    for (int b = 0; b < NB_STAT; b++) {
        s += g_part[b * 512 + tid];
        q += g_part[b * 512 + 256 + tid];
    }
    float m   = s * invN;
    float var = q * invN - m * m;
    g_mean[tid] = m;
    g_istd[tid] = rsqrtf(var + 1e-5f);
}

__global__ void bn_apply_kernel(const float* __restrict__ gamma,
                                const float* __restrict__ beta,
                                float* __restrict__ out, long long nq4) {
    long long t = (long long)blockIdx.x * blockDim.x + threadIdx.x;
    if (t >= nq4) return;
    int c4 = (int)(t & 63);   // float4 column index (D/4 = 64)
    float4 v = ((const float4*)g_h2)[t];
    float4 m = ((const float4*)g_mean)[c4];
    float4 is = ((const float4*)g_istd)[c4];
    float4 g = ((const float4*)gamma)[c4];
    float4 b = ((const float4*)beta)[c4];
    float4 o;
    o.x = (v.x - m.x) * is.x * g.x + b.x;
    o.y = (v.y - m.y) * is.y * g.y + b.y;
    o.z = (v.z - m.z) * is.z * g.z + b.z;
    o.w = (v.w - m.w) * is.w * g.w + b.w;
    ((float4*)out)[t] = o;
}

// ---------------------------------------------------------------------------
// Launch
// ---------------------------------------------------------------------------
extern "C" void kernel_launch(void* const* d_in, const int* in_sizes, int n_in,
                              void* d_out, int out_size) {
    const float* x     = (const float*)d_in[0];
    const void*  src   = d_in[1];
    const void*  dst   = d_in[2];
    const float* eps   = (const float*)d_in[3];
    const float* W1    = (const float*)d_in[4];
    const float* b1    = (const float*)d_in[5];
    const float* W2    = (const float*)d_in[6];
    const float* b2    = (const float*)d_in[7];
    const float* gamma = (const float*)d_in[8];
    const float* beta  = (const float*)d_in[9];
    float* out = (float*)d_out;

    const long long n = (long long)in_sizes[0] / DIM;   // 100000
    const long long e = (long long)in_sizes[1];         // 1600000

    float *agg, *h1, *h2;
    cudaGetSymbolAddress((void**)&agg, g_agg);
    cudaGetSymbolAddress((void**)&h1,  g_h1);
    cudaGetSymbolAddress((void**)&h2,  g_h2);

    // 0) index-dtype detection
    detect_idx_kernel<<<1, 1>>>((const int*)src);

    // 1) accumulator seed
    long long nq4 = n * DIM / 4;
    init_agg_kernel<<<(int)((nq4 + 255) / 256), 256>>>(x, eps, nq4);

    // 2) edge scatter-sum
    long long total = e * 64;
    scatter_kernel<<<(int)((total + 255) / 256), 256>>>(x, src, dst, e);

    // 3) MLP
    dim3 g1(DIM2 / 128, (unsigned)((n + 127) / 128));
    sgemm_kernel<<<g1, 256>>>(agg, W1, b1, h1, (int)n, DIM, DIM2, 1);
    dim3 g2(DIM / 128, (unsigned)((n + 127) / 128));
    sgemm_kernel<<<g2, 256>>>(h1, W2, b2, h2, (int)n, DIM2, DIM, 0);

    // 4) BatchNorm (training-mode batch stats, biased variance)
    bn_partial_kernel<<<NB_STAT, 256>>>(n);
    bn_finalize_kernel<<<1, 256>>>(1.0f / (float)n);
    bn_apply_kernel<<<(int)((nq4 + 255) / 256), 256>>>(gamma, beta, out, nq4);
}

// round 7
// speedup vs baseline: 1.8011x; 1.8011x over previous
#include <cuda_runtime.h>
#include <cuda_fp16.h>

// ---------------------------------------------------------------------------
// GIN layer: out = BN( relu( ((1+eps)x + scatter_sum(x[src]->dst)) @ W1 + b1 ) @ W2 + b2 )
// N=100000, D=256, E=1600000.
// MLP on HMMA (mma.sync.m16n8k16 fp16) with split-fp16 (hi/lo) folded into K.
// ---------------------------------------------------------------------------

#define NNODE 100000
#define MPAD  100096          // 782 * 128
#define DIM   256
#define DIM2  512
#define KA1   512             // [hi(256) | lo(256)]
#define KA2   1024            // [hi(512) | lo(512)]

constexpr int NB_STAT = 1184;

typedef unsigned int u32;

// ----------------------------- scratch (globals) ---------------------------
__device__ __align__(1024) float  g_agg[(size_t)NNODE * DIM];
__device__ __align__(1024) float  g_h2 [(size_t)NNODE * DIM];
__device__ __align__(1024) __half g_A1[(size_t)MPAD * KA1];   // [hi|lo]
__device__ __align__(1024) __half g_A2[(size_t)MPAD * KA2];   // [hi|lo] (written by GEMM1 epi)
__device__ __align__(1024) __half g_B1[(size_t)DIM2 * KA1];   // W1^T fp16, duplicated: [w|w]
__device__ __align__(1024) __half g_B2[(size_t)DIM  * KA2];   // W2^T fp16, duplicated: [w|w]
__device__ float g_part[NB_STAT * 512];
__device__ float g_mean[DIM];
__device__ float g_istd[DIM];
__device__ int   g_idx64;

// ----------------------------- helpers -------------------------------------
__device__ __forceinline__ u32 smem_u32(const void* p) {
    u32 a;
    asm("{ .reg .u64 t; cvta.to.shared.u64 t, %1; cvt.u32.u64 %0, t; }" : "=r"(a) : "l"(p));
    return a;
}
__device__ __forceinline__ u32 sw128(u32 o) { return o ^ ((o >> 3) & 0x70); }

__device__ __forceinline__ void cp_async16(u32 saddr, const void* g) {
    asm volatile("cp.async.cg.shared.global [%0], [%1], 16;" :: "r"(saddr), "l"(g));
}
#define CP_COMMIT()  asm volatile("cp.async.commit_group;")
#define CP_WAIT(n)   asm volatile("cp.async.wait_group %0;" :: "n"(n) : "memory")

__device__ __forceinline__ void ldsm4(u32& r0, u32& r1, u32& r2, u32& r3, u32 addr) {
    asm volatile("ldmatrix.sync.aligned.m8n8.x4.shared.b16 {%0,%1,%2,%3}, [%4];"
                 : "=r"(r0), "=r"(r1), "=r"(r2), "=r"(r3) : "r"(addr));
}

__device__ __forceinline__ void mma16816(float* c, const u32* a, u32 b0, u32 b1) {
    asm volatile(
        "mma.sync.aligned.m16n8k16.row.col.f32.f16.f16.f32 "
        "{%0,%1,%2,%3}, {%4,%5,%6,%7}, {%8,%9}, {%0,%1,%2,%3};"
        : "+f"(c[0]), "+f"(c[1]), "+f"(c[2]), "+f"(c[3])
        : "r"(a[0]), "r"(a[1]), "r"(a[2]), "r"(a[3]), "r"(b0), "r"(b1));
}

// ---------------------------------------------------------------------------
// index dtype detection
// ---------------------------------------------------------------------------
__global__ void detect_idx_kernel(const int* __restrict__ w) {
    int z = 1;
    for (int i = 1; i < 129; i += 2) if (w[i] != 0) { z = 0; break; }
    g_idx64 = z;
}
__device__ __forceinline__ long long load_idx(const void* p, long long i) {
    if (g_idx64) return ((const long long*)p)[i];
    return (long long)((const int*)p)[i];
}

// ---------------------------------------------------------------------------
// aggregation: g_agg = (1+eps)*x, then scatter-add with red.global.add.v4
// ---------------------------------------------------------------------------
__global__ void init_agg_kernel(const float* __restrict__ x,
                                const float* __restrict__ eps, long long nq4) {
    const float s = 1.0f + eps[0];
    long long t = (long long)blockIdx.x * blockDim.x + threadIdx.x;
    if (t >= nq4) return;
    float4 v = ((const float4*)x)[t];
    v.x *= s; v.y *= s; v.z *= s; v.w *= s;
    ((float4*)g_agg)[t] = v;
}

__global__ void scatter_kernel(const float* __restrict__ x,
                               const void* __restrict__ src,
                               const void* __restrict__ dst, long long ne) {
    long long t = (long long)blockIdx.x * blockDim.x + threadIdx.x;
    if (t >= ne * 64) return;
    long long e = t >> 6;
    int c = (int)(t & 63);
    long long s = load_idx(src, e);
    long long d = load_idx(dst, e);
    float4 v = ((const float4*)(x + s * DIM))[c];
    float* a = g_agg + d * DIM + (long long)c * 4;
    asm volatile("red.global.add.v4.f32 [%0], {%1,%2,%3,%4};"
                 :: "l"(a), "f"(v.x), "f"(v.y), "f"(v.z), "f"(v.w) : "memory");
}

// ---------------------------------------------------------------------------
// conversions (split-fp16 layouts)
// ---------------------------------------------------------------------------
__device__ __forceinline__ void split_h(float v, __half& h, __half& l) {
    h = __float2half_rn(v);
    l = __float2half_rn(v - __half2float(h));
}

__global__ void conv_A1_kernel(long long total) {   // total = NNODE*64
    long long t = (long long)blockIdx.x * blockDim.x + threadIdx.x;
    if (t >= total) return;
    long long row = t >> 6;
    int c4 = (int)(t & 63) * 4;
    float4 v = *(const float4*)(g_agg + row * DIM + c4);
    __half h0,h1,h2,h3,l0,l1,l2,l3;
    split_h(v.x,h0,l0); split_h(v.y,h1,l1); split_h(v.z,h2,l2); split_h(v.w,h3,l3);
    uint2 hw, lw;
    hw.x = (u32)__half_as_ushort(h0) | ((u32)__half_as_ushort(h1) << 16);
    hw.y = (u32)__half_as_ushort(h2) | ((u32)__half_as_ushort(h3) << 16);
    lw.x = (u32)__half_as_ushort(l0) | ((u32)__half_as_ushort(l1) << 16);
    lw.y = (u32)__half_as_ushort(l2) | ((u32)__half_as_ushort(l3) << 16);
    __half* r = g_A1 + row * KA1;
    *(uint2*)(r + c4)       = hw;
    *(uint2*)(r + 256 + c4) = lw;
}

__global__ void conv_W1_kernel(const float* __restrict__ W1) {  // [256,512] -> g_B1 [512][512]
    int t = blockIdx.x * blockDim.x + threadIdx.x;
    if (t >= DIM * DIM2) return;
    int k = t >> 9, n = t & 511;
    __half h = __float2half_rn(W1[t]);
    __half* r = g_B1 + (size_t)n * KA1;
    r[k] = h; r[256 + k] = h;
}
__global__ void conv_W2_kernel(const float* __restrict__ W2) {  // [512,256] -> g_B2 [256][1024]
    int t = blockIdx.x * blockDim.x + threadIdx.x;
    if (t >= DIM2 * DIM) return;
    int k = t >> 8, n = t & 255;
    __half h = __float2half_rn(W2[t]);
    __half* r = g_B2 + (size_t)n * KA2;
    r[k] = h; r[512 + k] = h;
}

// ---------------------------------------------------------------------------
// HMMA GEMM: C[M, Ncols] tile 128x128 = A[M,KA] . B[Ncols,KA]^T, K-major fp16.
// 8 warps (4x2), warp tile 32x64, m16n8k16, cp.async double buffer, SW128.
// mode 1: relu(D + bias) -> split-fp16 -> g_A2 [hi|lo]
// mode 2: D + bias -> fp32 g_h2
// ---------------------------------------------------------------------------
#define SMEM_SZ 65536   // 2 * (16K A + 16K B)

__device__ __forceinline__ void load_tiles(u32 sA, u32 sB,
                                           const __half* A, const __half* B,
                                           int m0, int n0, int KA, int k0, int tid) {
#pragma unroll
    for (int l = 0; l < 4; l++) {                 // A: 128 rows x 4 chunks(16B)
        int i = tid + l * 256;
        int r = i >> 3, c = i & 7;
        cp_async16(sA + sw128((u32)(r * 128 + c * 16)),
                   A + (size_t)(m0 + r) * KA + k0 + c * 8);
    }
#pragma unroll
    for (int l = 0; l < 4; l++) {                 // B: 128 rows x 4 chunks
        int i = tid + l * 256;
        int r = i >> 3, c = i & 7;
        cp_async16(sB + sw128((u32)(r * 128 + c * 16)),
                   B + (size_t)(n0 + r) * KA + k0 + c * 8);
    }
}

__global__ void __launch_bounds__(256)
mma_gemm_kernel(const __half* __restrict__ A, const __half* __restrict__ B,
                const float* __restrict__ bias, int M, int KA, int mode) {
    extern __shared__ char smem[];
    const u32 sbase = smem_u32(smem);
    const int tid  = threadIdx.x;
    const int lane = tid & 31;
    const int warp = tid >> 5;
    const int m0 = blockIdx.y * 128;
    const int n0 = blockIdx.x * 128;
    const int wm = (warp & 3) * 32;
    const int wn = (warp >> 2) * 64;

    const u32 sA[2] = { sbase,         sbase + 32768 };
    const u32 sB[2] = { sbase + 16384, sbase + 49152 };

    float acc[2][8][4];
#pragma unroll
    for (int mt = 0; mt < 2; mt++)
#pragma unroll
        for (int j = 0; j < 8; j++)
#pragma unroll
            for (int q = 0; q < 4; q++) acc[mt][j][q] = 0.f;

    const int NT = KA >> 6;
    load_tiles(sA[0], sB[0], A, B, m0, n0, KA, 0, tid);
    CP_COMMIT();

    for (int t = 0; t < NT; t++) {
        if (t + 1 < NT) {
            load_tiles(sA[(t + 1) & 1], sB[(t + 1) & 1], A, B, m0, n0, KA, (t + 1) << 6, tid);
            CP_COMMIT();
            CP_WAIT(1);
        } else {
            CP_WAIT(0);
        }
        __syncthreads();

        const u32 a_base = sA[t & 1];
        const u32 b_base = sB[t & 1];
        const int ro = lane & 15;
        const int co = (lane >> 4) * 16;
#pragma unroll
        for (int ks = 0; ks < 4; ks++) {
            u32 a[2][4], b[4][4];
#pragma unroll
            for (int mt = 0; mt < 2; mt++)
                ldsm4(a[mt][0], a[mt][1], a[mt][2], a[mt][3],
                      a_base + sw128((u32)((wm + mt * 16 + ro) * 128 + ks * 32 + co)));
#pragma unroll
            for (int ng = 0; ng < 4; ng++)
                ldsm4(b[ng][0], b[ng][1], b[ng][2], b[ng][3],
                      b_base + sw128((u32)((wn + ng * 16 + ro) * 128 + ks * 32 + co)));
#pragma unroll
            for (int mt = 0; mt < 2; mt++)
#pragma unroll
                for (int j = 0; j < 8; j++)
                    mma16816(acc[mt][j], a[mt], b[j >> 1][j & 1], b[j >> 1][(j & 1) + 2]);
        }
        __syncthreads();
    }

    // ---------------- epilogue ----------------
    const int rbase = m0 + wm + (lane >> 2);
    const int cbase = n0 + wn + (lane & 3) * 2;
#pragma unroll
    for (int mt = 0; mt < 2; mt++) {
#pragma unroll
        for (int half = 0; half < 2; half++) {
            const int row = rbase + mt * 16 + half * 8;
            if (row >= M) continue;
            if (mode == 1) {
                __half* ar = g_A2 + (size_t)row * KA2;
#pragma unroll
                for (int j = 0; j < 8; j++) {
                    const int col = cbase + j * 8;
                    float v0 = acc[mt][j][half * 2 + 0] + __ldg(bias + col);
                    float v1 = acc[mt][j][half * 2 + 1] + __ldg(bias + col + 1);
                    v0 = fmaxf(v0, 0.f); v1 = fmaxf(v1, 0.f);
                    __half h0, l0, h1, l1;
                    split_h(v0, h0, l0); split_h(v1, h1, l1);
                    u32 hw = (u32)__half_as_ushort(h0) | ((u32)__half_as_ushort(h1) << 16);
                    u32 lw = (u32)__half_as_ushort(l0) | ((u32)__half_as_ushort(l1) << 16);
                    *(u32*)(ar + col)       = hw;
                    *(u32*)(ar + 512 + col) = lw;
                }
            } else {
                float* orow = g_h2 + (size_t)row * DIM;
#pragma unroll
                for (int j = 0; j < 8; j++) {
                    const int col = cbase + j * 8;
                    float2 v;
                    v.x = acc[mt][j][half * 2 + 0] + __ldg(bias + col);
                    v.y = acc[mt][j][half * 2 + 1] + __ldg(bias + col + 1);
                    *(float2*)(orow + col) = v;
                }
            }
        }
    }
}

// ---------------------------------------------------------------------------
// BatchNorm
// ---------------------------------------------------------------------------
__global__ void bn_partial_kernel(long long n) {
    int tid = threadIdx.x;
    float s = 0.f, q = 0.f;
    for (long long r = blockIdx.x; r < n; r += gridDim.x) {
        float v = g_h2[r * DIM + tid];
        s += v; q += v * v;
    }
    g_part[blockIdx.x * 512 + tid]       = s;
    g_part[blockIdx.x * 512 + 256 + tid] = q;
}
__global__ void bn_finalize_kernel(float invN) {
    int tid = threadIdx.x;
    float s = 0.f, q = 0.f;
    for (int b = 0; b < NB_STAT; b++) {
        s += g_part[b * 512 + tid];
        q += g_part[b * 512 + 256 + tid];
    }
    float m = s * invN;
    g_mean[tid] = m;
    g_istd[tid] = rsqrtf(q * invN - m * m + 1e-5f);
}
__global__ void bn_apply_kernel(const float* __restrict__ gamma,
                                const float* __restrict__ beta,
                                float* __restrict__ out, long long nq4) {
    long long t = (long long)blockIdx.x * blockDim.x + threadIdx.x;
    if (t >= nq4) return;
    int c4 = (int)(t & 63);
    float4 v  = ((const float4*)g_h2)[t];
    float4 m  = ((const float4*)g_mean)[c4];
    float4 is = ((const float4*)g_istd)[c4];
    float4 g  = ((const float4*)gamma)[c4];
    float4 b  = ((const float4*)beta)[c4];
    float4 o;
    o.x = (v.x - m.x) * is.x * g.x + b.x;
    o.y = (v.y - m.y) * is.y * g.y + b.y;
    o.z = (v.z - m.z) * is.z * g.z + b.z;
    o.w = (v.w - m.w) * is.w * g.w + b.w;
    ((float4*)out)[t] = o;
}

// ---------------------------------------------------------------------------
// launch
// ---------------------------------------------------------------------------
extern "C" void kernel_launch(void* const* d_in, const int* in_sizes, int n_in,
                              void* d_out, int out_size) {
    const float* x     = (const float*)d_in[0];
    const void*  src   = d_in[1];
    const void*  dst   = d_in[2];
    const float* eps   = (const float*)d_in[3];
    const float* W1    = (const float*)d_in[4];
    const float* b1    = (const float*)d_in[5];
    const float* W2    = (const float*)d_in[6];
    const float* b2    = (const float*)d_in[7];
    const float* gamma = (const float*)d_in[8];
    const float* beta  = (const float*)d_in[9];
    float* out = (float*)d_out;

    const long long n = (long long)in_sizes[0] / DIM;   // 100000
    const long long e = (long long)in_sizes[1];         // 1600000

    __half *A1, *A2, *B1, *B2;
    cudaGetSymbolAddress((void**)&A1, g_A1);
    cudaGetSymbolAddress((void**)&A2, g_A2);
    cudaGetSymbolAddress((void**)&B1, g_B1);
    cudaGetSymbolAddress((void**)&B2, g_B2);

    cudaFuncSetAttribute(mma_gemm_kernel, cudaFuncAttributeMaxDynamicSharedMemorySize, SMEM_SZ);

    // 0) index dtype
    detect_idx_kernel<<<1, 1>>>((const int*)src);

    // 1) seed accumulator + scatter
    long long nq4 = n * DIM / 4;
    init_agg_kernel<<<(int)((nq4 + 255) / 256), 256>>>(x, eps, nq4);
    long long total = e * 64;
    scatter_kernel<<<(int)((total + 255) / 256), 256>>>(x, src, dst, e);

    // 2) conversions
    conv_W1_kernel<<<(DIM * DIM2 + 255) / 256, 256>>>(W1);
    conv_W2_kernel<<<(DIM2 * DIM + 255) / 256, 256>>>(W2);
    long long ca = n * 64;
    conv_A1_kernel<<<(int)((ca + 255) / 256), 256>>>(ca);

    // 3) MLP on HMMA tensor cores (split-fp16)
    int mtiles = MPAD / 128;    // 782
    dim3 g1(DIM2 / 128, mtiles);
    mma_gemm_kernel<<<g1, 256, SMEM_SZ>>>(A1, B1, b1, (int)n, KA1, 1);
    dim3 g2(DIM / 128, mtiles);
    mma_gemm_kernel<<<g2, 256, SMEM_SZ>>>(A2, B2, b2, (int)n, KA2, 2);

    // 4) BatchNorm
    bn_partial_kernel<<<NB_STAT, 256>>>(n);
    bn_finalize_kernel<<<1, 256>>>(1.0f / (float)n);
    bn_apply_kernel<<<(int)((nq4 + 255) / 256), 256>>>(gamma, beta, out, nq4);
}

// round 9
// speedup vs baseline: 2.1318x; 1.1836x over previous
#include <cuda_runtime.h>
#include <cuda_fp16.h>

// ---------------------------------------------------------------------------
// GIN layer: out = BN( relu( ((1+eps)x + scatter_sum(x[src]->dst)) @ W1 + b1 ) @ W2 + b2 )
// N=100000, D=256, E=1600000.
// Aggregation via CSR counting-sort + register gather (no fp32 atomics).
// MLP on HMMA (mma.sync.m16n8k16 fp16) with split-fp16 (hi/lo) folded into K.
// BN stats fused into GEMM2 epilogue.
// ---------------------------------------------------------------------------

#define NNODE 100000
#define MPAD  100096          // 782 * 128
#define EMAX  1600000
#define DIM   256
#define DIM2  512
#define KA1   512             // [hi(256) | lo(256)]
#define KA2   1024            // [hi(512) | lo(512)]

typedef unsigned int u32;

// ----------------------------- scratch (globals) ---------------------------
__device__ __align__(1024) float  g_h2 [(size_t)NNODE * DIM];
__device__ __align__(1024) __half g_A1[(size_t)MPAD * KA1];   // [hi|lo]  (pad rows stay 0)
__device__ __align__(1024) __half g_A2[(size_t)MPAD * KA2];   // [hi|lo]  (pad rows stay 0)
__device__ __align__(1024) __half g_B1[(size_t)DIM2 * KA1];   // W1^T fp16 dup [w|w]
__device__ __align__(1024) __half g_B2[(size_t)DIM  * KA2];   // W2^T fp16 dup [w|w]
__device__ int   g_deg[NNODE];
__device__ int   g_off[NNODE];
__device__ int   g_cursor[NNODE];
__device__ int   g_csr[EMAX];
__device__ int   g_bsum[128];
__device__ int   g_boff[128];
__device__ float g_colsum[DIM];
__device__ float g_colsq[DIM];
__device__ float g_mean[DIM];
__device__ float g_istd[DIM];
__device__ int   g_idx64;

// ----------------------------- helpers -------------------------------------
__device__ __forceinline__ u32 smem_u32(const void* p) {
    u32 a;
    asm("{ .reg .u64 t; cvta.to.shared.u64 t, %1; cvt.u32.u64 %0, t; }" : "=r"(a) : "l"(p));
    return a;
}
__device__ __forceinline__ u32 sw128(u32 o) { return o ^ ((o >> 3) & 0x70); }

__device__ __forceinline__ void cp_async16(u32 saddr, const void* g) {
    asm volatile("cp.async.cg.shared.global [%0], [%1], 16;" :: "r"(saddr), "l"(g));
}
#define CP_COMMIT()  asm volatile("cp.async.commit_group;")
#define CP_WAIT(n)   asm volatile("cp.async.wait_group %0;" :: "n"(n) : "memory")

__device__ __forceinline__ void ldsm4(u32& r0, u32& r1, u32& r2, u32& r3, u32 addr) {
    asm volatile("ldmatrix.sync.aligned.m8n8.x4.shared.b16 {%0,%1,%2,%3}, [%4];"
                 : "=r"(r0), "=r"(r1), "=r"(r2), "=r"(r3) : "r"(addr));
}
__device__ __forceinline__ void mma16816(float* c, const u32* a, u32 b0, u32 b1) {
    asm volatile(
        "mma.sync.aligned.m16n8k16.row.col.f32.f16.f16.f32 "
        "{%0,%1,%2,%3}, {%4,%5,%6,%7}, {%8,%9}, {%0,%1,%2,%3};"
        : "+f"(c[0]), "+f"(c[1]), "+f"(c[2]), "+f"(c[3])
        : "r"(a[0]), "r"(a[1]), "r"(a[2]), "r"(a[3]), "r"(b0), "r"(b1));
}

__device__ __forceinline__ void split_h(float v, __half& h, __half& l) {
    h = __float2half_rn(v);
    l = __float2half_rn(v - __half2float(h));
}
__device__ __forceinline__ void pack_hl(float4 v, uint2& hw, uint2& lw) {
    __half h0,h1,h2,h3,l0,l1,l2,l3;
    split_h(v.x,h0,l0); split_h(v.y,h1,l1); split_h(v.z,h2,l2); split_h(v.w,h3,l3);
    hw.x = (u32)__half_as_ushort(h0) | ((u32)__half_as_ushort(h1) << 16);
    hw.y = (u32)__half_as_ushort(h2) | ((u32)__half_as_ushort(h3) << 16);
    lw.x = (u32)__half_as_ushort(l0) | ((u32)__half_as_ushort(l1) << 16);
    lw.y = (u32)__half_as_ushort(l2) | ((u32)__half_as_ushort(l3) << 16);
}

// ---------------------------------------------------------------------------
// index dtype detection
// ---------------------------------------------------------------------------
__global__ void detect_idx_kernel(const int* __restrict__ w) {
    int z = 1;
    for (int i = 1; i < 129; i += 2) if (w[i] != 0) { z = 0; break; }
    g_idx64 = z;
}
__device__ __forceinline__ int load_idx(const void* p, long long i) {
    if (g_idx64) return (int)((const long long*)p)[i];
    return ((const int*)p)[i];
}

// ---------------------------------------------------------------------------
// CSR build: zero -> histogram(dst) -> exclusive scan -> fill
// ---------------------------------------------------------------------------
__global__ void zero_kernel(int n) {
    int t = blockIdx.x * blockDim.x + threadIdx.x;
    if (t < n) g_deg[t] = 0;
    if (t < DIM) { g_colsum[t] = 0.f; g_colsq[t] = 0.f; }
}
__global__ void hist_kernel(const void* __restrict__ dst, long long ne) {
    long long e = (long long)blockIdx.x * blockDim.x + threadIdx.x;
    if (e >= ne) return;
    atomicAdd(&g_deg[load_idx(dst, e)], 1);
}
__global__ void scan1_kernel(int n) {
    __shared__ int sh[1024];
    int gid = blockIdx.x * 1024 + threadIdx.x;
    int v = (gid < n) ? g_deg[gid] : 0;
    sh[threadIdx.x] = v;
    __syncthreads();
#pragma unroll
    for (int off = 1; off < 1024; off <<= 1) {
        int t = (threadIdx.x >= off) ? sh[threadIdx.x - off] : 0;
        __syncthreads();
        sh[threadIdx.x] += t;
        __syncthreads();
    }
    if (gid < n) g_off[gid] = sh[threadIdx.x] - v;      // block-local exclusive
    if (threadIdx.x == 1023) g_bsum[blockIdx.x] = sh[1023];
}
__global__ void scan2_kernel(int nb) {
    __shared__ int sh[128];
    int v = (threadIdx.x < nb) ? g_bsum[threadIdx.x] : 0;
    sh[threadIdx.x] = v;
    __syncthreads();
#pragma unroll
    for (int off = 1; off < 128; off <<= 1) {
        int t = (threadIdx.x >= off) ? sh[threadIdx.x - off] : 0;
        __syncthreads();
        sh[threadIdx.x] += t;
        __syncthreads();
    }
    if (threadIdx.x < nb) g_boff[threadIdx.x] = sh[threadIdx.x] - v;
}
__global__ void scan3_kernel(int n) {
    int t = blockIdx.x * blockDim.x + threadIdx.x;
    if (t >= n) return;
    int o = g_off[t] + g_boff[t >> 10];
    g_off[t] = o;
    g_cursor[t] = o;
}
__global__ void fill_kernel(const void* __restrict__ src,
                            const void* __restrict__ dst, long long ne) {
    long long e = (long long)blockIdx.x * blockDim.x + threadIdx.x;
    if (e >= ne) return;
    int s = load_idx(src, e);
    int d = load_idx(dst, e);
    int pos = atomicAdd(&g_cursor[d], 1);
    g_csr[pos] = s;
}

// ---------------------------------------------------------------------------
// gather + seed + fp16 split: one warp per node
// A1[node] = split_fp16( (1+eps)*x[node] + sum_{s in N(node)} x[s] )
// ---------------------------------------------------------------------------
__global__ void __launch_bounds__(256)
gather_kernel(const float* __restrict__ x, const float* __restrict__ eps, int n) {
    int node = blockIdx.x * 8 + (threadIdx.x >> 5);
    if (node >= n) return;
    const int lane = threadIdx.x & 31;
    const int start = g_off[node];
    const int deg   = g_deg[node];

    float4 a0 = make_float4(0.f, 0.f, 0.f, 0.f);
    float4 a1 = make_float4(0.f, 0.f, 0.f, 0.f);

    for (int base = 0; base < deg; base += 32) {
        const int cnt = min(32, deg - base);
        int sj = 0;
        if (lane < cnt) sj = g_csr[start + base + lane];
        for (int k = 0; k < cnt; k++) {
            int s = __shfl_sync(0xffffffffu, sj, k);
            const float4* r = (const float4*)(x + (size_t)s * DIM);
            float4 v0 = __ldg(r + lane);
            float4 v1 = __ldg(r + lane + 32);
            a0.x += v0.x; a0.y += v0.y; a0.z += v0.z; a0.w += v0.w;
            a1.x += v1.x; a1.y += v1.y; a1.z += v1.z; a1.w += v1.w;
        }
    }

    const float sc = 1.0f + eps[0];
    const float4* xr = (const float4*)(x + (size_t)node * DIM);
    float4 v0 = __ldg(xr + lane), v1 = __ldg(xr + lane + 32);
    a0.x = fmaf(sc, v0.x, a0.x); a0.y = fmaf(sc, v0.y, a0.y);
    a0.z = fmaf(sc, v0.z, a0.z); a0.w = fmaf(sc, v0.w, a0.w);
    a1.x = fmaf(sc, v1.x, a1.x); a1.y = fmaf(sc, v1.y, a1.y);
    a1.z = fmaf(sc, v1.z, a1.z); a1.w = fmaf(sc, v1.w, a1.w);

    uint2 hw0, lw0, hw1, lw1;
    pack_hl(a0, hw0, lw0);
    pack_hl(a1, hw1, lw1);
    __half* ar = g_A1 + (size_t)node * KA1;
    *(uint2*)(ar + 4 * lane)       = hw0;   // hi cols   0..127
    *(uint2*)(ar + 128 + 4 * lane) = hw1;   // hi cols 128..255
    *(uint2*)(ar + 256 + 4 * lane) = lw0;   // lo cols   0..127
    *(uint2*)(ar + 384 + 4 * lane) = lw1;   // lo cols 128..255
}

// ---------------------------------------------------------------------------
// weight conversions
// ---------------------------------------------------------------------------
__global__ void conv_W1_kernel(const float* __restrict__ W1) {  // [256,512] -> g_B1 [512][512]
    int t = blockIdx.x * blockDim.x + threadIdx.x;
    if (t >= DIM * DIM2) return;
    int k = t >> 9, n = t & 511;
    __half h = __float2half_rn(W1[t]);
    __half* r = g_B1 + (size_t)n * KA1;
    r[k] = h; r[256 + k] = h;
}
__global__ void conv_W2_kernel(const float* __restrict__ W2) {  // [512,256] -> g_B2 [256][1024]
    int t = blockIdx.x * blockDim.x + threadIdx.x;
    if (t >= DIM2 * DIM) return;
    int k = t >> 8, n = t & 255;
    __half h = __float2half_rn(W2[t]);
    __half* r = g_B2 + (size_t)n * KA2;
    r[k] = h; r[512 + k] = h;
}

// ---------------------------------------------------------------------------
// HMMA GEMM: 128x128 CTA tile, 8 warps (32x64), m16n8k16, cp.async dbuf, SW128.
// mode 1: relu(D + bias) -> split-fp16 -> g_A2 [hi|lo]
// mode 2: D + bias -> fp32 g_h2, plus fused BN column sum/sumsq atomics
// ---------------------------------------------------------------------------
#define SMEM_SZ 65536

__device__ __forceinline__ void load_tiles(u32 sA, u32 sB,
                                           const __half* A, const __half* B,
                                           int m0, int n0, int KA, int k0, int tid) {
#pragma unroll
    for (int l = 0; l < 4; l++) {
        int i = tid + l * 256;
        int r = i >> 3, c = i & 7;
        cp_async16(sA + sw128((u32)(r * 128 + c * 16)),
                   A + (size_t)(m0 + r) * KA + k0 + c * 8);
    }
#pragma unroll
    for (int l = 0; l < 4; l++) {
        int i = tid + l * 256;
        int r = i >> 3, c = i & 7;
        cp_async16(sB + sw128((u32)(r * 128 + c * 16)),
                   B + (size_t)(n0 + r) * KA + k0 + c * 8);
    }
}

__global__ void __launch_bounds__(256)
mma_gemm_kernel(const __half* __restrict__ A, const __half* __restrict__ B,
                const float* __restrict__ bias, int M, int KA, int mode) {
    extern __shared__ char smem[];
    const u32 sbase = smem_u32(smem);
    const int tid  = threadIdx.x;
    const int lane = tid & 31;
    const int warp = tid >> 5;
    const int m0 = blockIdx.y * 128;
    const int n0 = blockIdx.x * 128;
    const int wm = (warp & 3) * 32;
    const int wn = (warp >> 2) * 64;

    const u32 sA[2] = { sbase,         sbase + 32768 };
    const u32 sB[2] = { sbase + 16384, sbase + 49152 };

    float acc[2][8][4];
#pragma unroll
    for (int mt = 0; mt < 2; mt++)
#pragma unroll
        for (int j = 0; j < 8; j++)
#pragma unroll
            for (int q = 0; q < 4; q++) acc[mt][j][q] = 0.f;

    const int NT = KA >> 6;
    load_tiles(sA[0], sB[0], A, B, m0, n0, KA, 0, tid);
    CP_COMMIT();

    for (int t = 0; t < NT; t++) {
        if (t + 1 < NT) {
            load_tiles(sA[(t + 1) & 1], sB[(t + 1) & 1], A, B, m0, n0, KA, (t + 1) << 6, tid);
            CP_COMMIT();
            CP_WAIT(1);
        } else {
            CP_WAIT(0);
        }
        __syncthreads();

        const u32 a_base = sA[t & 1];
        const u32 b_base = sB[t & 1];
        const int ro = lane & 15;
        const int co = (lane >> 4) * 16;
#pragma unroll
        for (int ks = 0; ks < 4; ks++) {
            u32 a[2][4], b[4][4];
#pragma unroll
            for (int mt = 0; mt < 2; mt++)
                ldsm4(a[mt][0], a[mt][1], a[mt][2], a[mt][3],
                      a_base + sw128((u32)((wm + mt * 16 + ro) * 128 + ks * 32 + co)));
#pragma unroll
            for (int ng = 0; ng < 4; ng++)
                ldsm4(b[ng][0], b[ng][1], b[ng][2], b[ng][3],
                      b_base + sw128((u32)((wn + ng * 16 + ro) * 128 + ks * 32 + co)));
#pragma unroll
            for (int mt = 0; mt < 2; mt++)
#pragma unroll
                for (int j = 0; j < 8; j++)
                    mma16816(acc[mt][j], a[mt], b[j >> 1][j & 1], b[j >> 1][(j & 1) + 2]);
        }
        __syncthreads();
    }

    // ---------------- epilogue ----------------
    const int rbase = m0 + wm + (lane >> 2);
    const int cbase = n0 + wn + (lane & 3) * 2;

    float cs[8][2], cq[8][2];
    if (mode == 2) {
#pragma unroll
        for (int j = 0; j < 8; j++) { cs[j][0]=cs[j][1]=cq[j][0]=cq[j][1]=0.f; }
    }

#pragma unroll
    for (int mt = 0; mt < 2; mt++) {
#pragma unroll
        for (int half = 0; half < 2; half++) {
            const int row = rbase + mt * 16 + half * 8;
            if (row >= M) continue;
            if (mode == 1) {
                __half* ar = g_A2 + (size_t)row * KA2;
#pragma unroll
                for (int j = 0; j < 8; j++) {
                    const int col = cbase + j * 8;
                    float v0 = acc[mt][j][half * 2 + 0] + __ldg(bias + col);
                    float v1 = acc[mt][j][half * 2 + 1] + __ldg(bias + col + 1);
                    v0 = fmaxf(v0, 0.f); v1 = fmaxf(v1, 0.f);
                    __half h0, l0, h1, l1;
                    split_h(v0, h0, l0); split_h(v1, h1, l1);
                    u32 hw = (u32)__half_as_ushort(h0) | ((u32)__half_as_ushort(h1) << 16);
                    u32 lw = (u32)__half_as_ushort(l0) | ((u32)__half_as_ushort(l1) << 16);
                    *(u32*)(ar + col)       = hw;
                    *(u32*)(ar + 512 + col) = lw;
                }
            } else {
                float* orow = g_h2 + (size_t)row * DIM;
#pragma unroll
                for (int j = 0; j < 8; j++) {
                    const int col = cbase + j * 8;
                    float2 v;
                    v.x = acc[mt][j][half * 2 + 0] + __ldg(bias + col);
                    v.y = acc[mt][j][half * 2 + 1] + __ldg(bias + col + 1);
                    *(float2*)(orow + col) = v;
                    cs[j][0] += v.x;  cs[j][1] += v.y;
                    cq[j][0] += v.x * v.x;  cq[j][1] += v.y * v.y;
                }
            }
        }
    }

    if (mode == 2) {
        // reduce across the 8 threads (lane bits 2,3,4) sharing each column
#pragma unroll
        for (int j = 0; j < 8; j++) {
#pragma unroll
            for (int c = 0; c < 2; c++) {
                float s = cs[j][c], q = cq[j][c];
#pragma unroll
                for (int o = 4; o < 32; o <<= 1) {
                    s += __shfl_xor_sync(0xffffffffu, s, o);
                    q += __shfl_xor_sync(0xffffffffu, q, o);
                }
                if ((lane >> 2) == 0) {
                    const int col = (cbase & 255) + j * 8 + c;
                    atomicAdd(&g_colsum[col], s);
                    atomicAdd(&g_colsq[col],  q);
                }
            }
        }
    }
}

// ---------------------------------------------------------------------------
// BatchNorm finalize + apply
// ---------------------------------------------------------------------------
__global__ void bn_finalize_kernel(float invN) {
    int tid = threadIdx.x;
    float m = g_colsum[tid] * invN;
    g_mean[tid] = m;
    g_istd[tid] = rsqrtf(g_colsq[tid] * invN - m * m + 1e-5f);
}
__global__ void bn_apply_kernel(const float* __restrict__ gamma,
                                const float* __restrict__ beta,
                                float* __restrict__ out, long long nq4) {
    long long t = (long long)blockIdx.x * blockDim.x + threadIdx.x;
    if (t >= nq4) return;
    int c4 = (int)(t & 63);
    float4 v  = ((const float4*)g_h2)[t];
    float4 m  = ((const float4*)g_mean)[c4];
    float4 is = ((const float4*)g_istd)[c4];
    float4 g  = ((const float4*)gamma)[c4];
    float4 b  = ((const float4*)beta)[c4];
    float4 o;
    o.x = (v.x - m.x) * is.x * g.x + b.x;
    o.y = (v.y - m.y) * is.y * g.y + b.y;
    o.z = (v.z - m.z) * is.z * g.z + b.z;
    o.w = (v.w - m.w) * is.w * g.w + b.w;
    ((float4*)out)[t] = o;
}

// ---------------------------------------------------------------------------
// launch
// ---------------------------------------------------------------------------
extern "C" void kernel_launch(void* const* d_in, const int* in_sizes, int n_in,
                              void* d_out, int out_size) {
    const float* x     = (const float*)d_in[0];
    const void*  src   = d_in[1];
    const void*  dst   = d_in[2];
    const float* eps   = (const float*)d_in[3];
    const float* W1    = (const float*)d_in[4];
    const float* b1    = (const float*)d_in[5];
    const float* W2    = (const float*)d_in[6];
    const float* b2    = (const float*)d_in[7];
    const float* gamma = (const float*)d_in[8];
    const float* beta  = (const float*)d_in[9];
    float* out = (float*)d_out;

    const long long n = (long long)in_sizes[0] / DIM;   // 100000
    const long long e = (long long)in_sizes[1];         // 1600000
    const int ni = (int)n;
    const int nb1024 = (ni + 1023) / 1024;

    __half *A1, *A2, *B1, *B2;
    cudaGetSymbolAddress((void**)&A1, g_A1);
    cudaGetSymbolAddress((void**)&A2, g_A2);
    cudaGetSymbolAddress((void**)&B1, g_B1);
    cudaGetSymbolAddress((void**)&B2, g_B2);

    cudaFuncSetAttribute(mma_gemm_kernel, cudaFuncAttributeMaxDynamicSharedMemorySize, SMEM_SZ);

    // 0) index dtype
    detect_idx_kernel<<<1, 1>>>((const int*)src);

    // 1) CSR build
    zero_kernel<<<(ni + 255) / 256, 256>>>(ni);
    hist_kernel<<<(int)((e + 255) / 256), 256>>>(dst, e);
    scan1_kernel<<<nb1024, 1024>>>(ni);
    scan2_kernel<<<1, 128>>>(nb1024);
    scan3_kernel<<<(ni + 255) / 256, 256>>>(ni);
    fill_kernel<<<(int)((e + 255) / 256), 256>>>(src, dst, e);

    // 2) fused gather + seed + fp16 split (writes g_A1 directly)
    gather_kernel<<<(ni + 7) / 8, 256>>>(x, eps, ni);

    // 3) weight conversions
    conv_W1_kernel<<<(DIM * DIM2 + 255) / 256, 256>>>(W1);
    conv_W2_kernel<<<(DIM2 * DIM + 255) / 256, 256>>>(W2);

    // 4) MLP on HMMA (split-fp16); GEMM2 fuses BN stats
    int mtiles = MPAD / 128;    // 782
    dim3 g1(DIM2 / 128, mtiles);
    mma_gemm_kernel<<<g1, 256, SMEM_SZ>>>(A1, B1, b1, ni, KA1, 1);
    dim3 g2(DIM / 128, mtiles);
    mma_gemm_kernel<<<g2, 256, SMEM_SZ>>>(A2, B2, b2, ni, KA2, 2);

    // 5) BatchNorm
    bn_finalize_kernel<<<1, 256>>>(1.0f / (float)n);
    long long nq4 = n * DIM / 4;
    bn_apply_kernel<<<(int)((nq4 + 255) / 256), 256>>>(gamma, beta, out, nq4);
}

// round 10
// speedup vs baseline: 3.5466x; 1.6636x over previous
#include <cuda_runtime.h>
#include <cuda_fp16.h>

// ---------------------------------------------------------------------------
// GIN layer: out = BN( relu( ((1+eps)x + scatter_sum(x[src]->dst)) @ W1 + b1 ) @ W2 + b2 )
// N=100000, D=256, E=1600000.
// CSR counting-sort + 2-warp/node register gather; HMMA fp16 MLP
// (GEMM1: split-fp16 hi/lo folded into K; GEMM2: plain fp16); fused BN stats.
// ---------------------------------------------------------------------------

#define NNODE 100000
#define MPAD  100096          // 782 * 128
#define EMAX  1600000
#define DIM   256
#define DIM2  512
#define KA1   512             // GEMM1 K: [hi(256) | lo(256)]
#define KA2   512             // GEMM2 K: plain fp16 h1

typedef unsigned int u32;

// ----------------------------- scratch (globals) ---------------------------
__device__ __align__(1024) float  g_h2 [(size_t)NNODE * DIM];
__device__ __align__(1024) __half g_A1[(size_t)MPAD * KA1];   // [hi|lo]  (pad rows stay 0)
__device__ __align__(1024) __half g_A2[(size_t)MPAD * KA2];   // fp16 h1  (pad rows stay 0)
__device__ __align__(1024) __half g_B1[(size_t)DIM2 * KA1];   // W1^T fp16 dup [w|w]
__device__ __align__(1024) __half g_B2[(size_t)DIM  * KA2];   // W2^T fp16
__device__ int   g_deg[NNODE];
__device__ int   g_off[NNODE];
__device__ int   g_cursor[NNODE];
__device__ int   g_csr[EMAX];
__device__ int   g_bsum[128];
__device__ int   g_boff[128];
__device__ float g_colsum[DIM];
__device__ float g_colsq[DIM];
__device__ float g_mean[DIM];
__device__ float g_istd[DIM];
__device__ int   g_idx64;

// ----------------------------- helpers -------------------------------------
__device__ __forceinline__ u32 smem_u32(const void* p) {
    u32 a;
    asm("{ .reg .u64 t; cvta.to.shared.u64 t, %1; cvt.u32.u64 %0, t; }" : "=r"(a) : "l"(p));
    return a;
}
__device__ __forceinline__ u32 sw128(u32 o) { return o ^ ((o >> 3) & 0x70); }

__device__ __forceinline__ void cp_async16(u32 saddr, const void* g) {
    asm volatile("cp.async.cg.shared.global [%0], [%1], 16;" :: "r"(saddr), "l"(g));
}
#define CP_COMMIT()  asm volatile("cp.async.commit_group;")
#define CP_WAIT(n)   asm volatile("cp.async.wait_group %0;" :: "n"(n) : "memory")

__device__ __forceinline__ void ldsm4(u32& r0, u32& r1, u32& r2, u32& r3, u32 addr) {
    asm volatile("ldmatrix.sync.aligned.m8n8.x4.shared.b16 {%0,%1,%2,%3}, [%4];"
                 : "=r"(r0), "=r"(r1), "=r"(r2), "=r"(r3) : "r"(addr));
}
__device__ __forceinline__ void mma16816(float* c, const u32* a, u32 b0, u32 b1) {
    asm volatile(
        "mma.sync.aligned.m16n8k16.row.col.f32.f16.f16.f32 "
        "{%0,%1,%2,%3}, {%4,%5,%6,%7}, {%8,%9}, {%0,%1,%2,%3};"
        : "+f"(c[0]), "+f"(c[1]), "+f"(c[2]), "+f"(c[3])
        : "r"(a[0]), "r"(a[1]), "r"(a[2]), "r"(a[3]), "r"(b0), "r"(b1));
}

__device__ __forceinline__ void split_h(float v, __half& h, __half& l) {
    h = __float2half_rn(v);
    l = __float2half_rn(v - __half2float(h));
}
__device__ __forceinline__ void pack_hl(float4 v, uint2& hw, uint2& lw) {
    __half h0,h1,h2,h3,l0,l1,l2,l3;
    split_h(v.x,h0,l0); split_h(v.y,h1,l1); split_h(v.z,h2,l2); split_h(v.w,h3,l3);
    hw.x = (u32)__half_as_ushort(h0) | ((u32)__half_as_ushort(h1) << 16);
    hw.y = (u32)__half_as_ushort(h2) | ((u32)__half_as_ushort(h3) << 16);
    lw.x = (u32)__half_as_ushort(l0) | ((u32)__half_as_ushort(l1) << 16);
    lw.y = (u32)__half_as_ushort(l2) | ((u32)__half_as_ushort(l3) << 16);
}

// ---------------------------------------------------------------------------
// index dtype detection
// ---------------------------------------------------------------------------
__global__ void detect_idx_kernel(const int* __restrict__ w) {
    int z = 1;
    for (int i = 1; i < 129; i += 2) if (w[i] != 0) { z = 0; break; }
    g_idx64 = z;
}
__device__ __forceinline__ int load_idx(const void* p, long long i) {
    if (g_idx64) return (int)((const long long*)p)[i];
    return ((const int*)p)[i];
}

// ---------------------------------------------------------------------------
// CSR build: zero -> histogram(dst) -> exclusive scan -> fill
// ---------------------------------------------------------------------------
__global__ void zero_kernel(int n) {
    int t = blockIdx.x * blockDim.x + threadIdx.x;
    if (t < n) g_deg[t] = 0;
    if (t < DIM) { g_colsum[t] = 0.f; g_colsq[t] = 0.f; }
}
__global__ void hist_kernel(const void* __restrict__ dst, long long ne) {
    long long e = (long long)blockIdx.x * blockDim.x + threadIdx.x;
    if (e >= ne) return;
    atomicAdd(&g_deg[load_idx(dst, e)], 1);
}
__global__ void scan1_kernel(int n) {
    __shared__ int sh[1024];
    int gid = blockIdx.x * 1024 + threadIdx.x;
    int v = (gid < n) ? g_deg[gid] : 0;
    sh[threadIdx.x] = v;
    __syncthreads();
#pragma unroll
    for (int off = 1; off < 1024; off <<= 1) {
        int t = (threadIdx.x >= off) ? sh[threadIdx.x - off] : 0;
        __syncthreads();
        sh[threadIdx.x] += t;
        __syncthreads();
    }
    if (gid < n) g_off[gid] = sh[threadIdx.x] - v;      // block-local exclusive
    if (threadIdx.x == 1023) g_bsum[blockIdx.x] = sh[1023];
}
__global__ void scan2_kernel(int nb) {
    __shared__ int sh[128];
    int v = (threadIdx.x < nb) ? g_bsum[threadIdx.x] : 0;
    sh[threadIdx.x] = v;
    __syncthreads();
#pragma unroll
    for (int off = 1; off < 128; off <<= 1) {
        int t = (threadIdx.x >= off) ? sh[threadIdx.x - off] : 0;
        __syncthreads();
        sh[threadIdx.x] += t;
        __syncthreads();
    }
    if (threadIdx.x < nb) g_boff[threadIdx.x] = sh[threadIdx.x] - v;
}
__global__ void scan3_kernel(int n) {
    int t = blockIdx.x * blockDim.x + threadIdx.x;
    if (t >= n) return;
    int o = g_off[t] + g_boff[t >> 10];
    g_off[t] = o;
    g_cursor[t] = o;
}
__global__ void fill_kernel(const void* __restrict__ src,
                            const void* __restrict__ dst, long long ne) {
    long long e = (long long)blockIdx.x * blockDim.x + threadIdx.x;
    if (e >= ne) return;
    int s = load_idx(src, e);
    int d = load_idx(dst, e);
    int pos = atomicAdd(&g_cursor[d], 1);
    g_csr[pos] = s;
}

// ---------------------------------------------------------------------------
// gather + seed + fp16 split: TWO warps per node, each owns 128 columns.
// A1[node] = split_fp16( (1+eps)*x[node] + sum_{s in N(node)} x[s] )
// ---------------------------------------------------------------------------
__global__ void __launch_bounds__(256)
gather_kernel(const float* __restrict__ x, const float* __restrict__ eps, int n) {
    const int node = blockIdx.x * 4 + (threadIdx.x >> 6);
    if (node >= n) return;
    const int half = (threadIdx.x >> 5) & 1;     // 0: cols 0..127, 1: cols 128..255
    const int lane = threadIdx.x & 31;
    const int start = g_off[node];
    const int deg   = g_deg[node];
    const int coff  = half * 32 + lane;          // float4 index within row (0..63)
    const float4* xb = (const float4*)x;

    float4 a = make_float4(0.f, 0.f, 0.f, 0.f);

    for (int base = 0; base < deg; base += 32) {
        const int cnt = min(32, deg - base);
        int sj = 0;
        if (lane < cnt) sj = g_csr[start + base + lane];
        int k = 0;
        for (; k + 1 < cnt; k += 2) {
            int s0 = __shfl_sync(0xffffffffu, sj, k);
            int s1 = __shfl_sync(0xffffffffu, sj, k + 1);
            float4 v0 = __ldg(xb + (size_t)s0 * 64 + coff);
            float4 v1 = __ldg(xb + (size_t)s1 * 64 + coff);
            a.x += v0.x; a.y += v0.y; a.z += v0.z; a.w += v0.w;
            a.x += v1.x; a.y += v1.y; a.z += v1.z; a.w += v1.w;
        }
        if (k < cnt) {
            int s0 = __shfl_sync(0xffffffffu, sj, k);
            float4 v0 = __ldg(xb + (size_t)s0 * 64 + coff);
            a.x += v0.x; a.y += v0.y; a.z += v0.z; a.w += v0.w;
        }
    }

    const float sc = 1.0f + eps[0];
    float4 v = __ldg(xb + (size_t)node * 64 + coff);
    a.x = fmaf(sc, v.x, a.x); a.y = fmaf(sc, v.y, a.y);
    a.z = fmaf(sc, v.z, a.z); a.w = fmaf(sc, v.w, a.w);

    uint2 hw, lw;
    pack_hl(a, hw, lw);
    __half* ar = g_A1 + (size_t)node * KA1;
    *(uint2*)(ar + half * 128 + 4 * lane)       = hw;   // hi
    *(uint2*)(ar + 256 + half * 128 + 4 * lane) = lw;   // lo
}

// ---------------------------------------------------------------------------
// weight conversions
// ---------------------------------------------------------------------------
__global__ void conv_W1_kernel(const float* __restrict__ W1) {  // [256,512] -> g_B1 [512][512]
    int t = blockIdx.x * blockDim.x + threadIdx.x;
    if (t >= DIM * DIM2) return;
    int k = t >> 9, n = t & 511;
    __half h = __float2half_rn(W1[t]);
    __half* r = g_B1 + (size_t)n * KA1;
    r[k] = h; r[256 + k] = h;
}
__global__ void conv_W2_kernel(const float* __restrict__ W2) {  // [512,256] -> g_B2 [256][512]
    int t = blockIdx.x * blockDim.x + threadIdx.x;
    if (t >= DIM2 * DIM) return;
    int k = t >> 8, n = t & 255;
    g_B2[(size_t)n * KA2 + k] = __float2half_rn(W2[t]);
}

// ---------------------------------------------------------------------------
// HMMA GEMM: 128x128 CTA tile, 8 warps (32x64), m16n8k16, cp.async dbuf, SW128.
// mode 1: relu(D + bias) -> plain fp16 -> g_A2
// mode 2: D + bias -> fp32 g_h2, plus fused BN column sum/sumsq atomics
// ---------------------------------------------------------------------------
#define SMEM_SZ 65536

__device__ __forceinline__ void load_tiles(u32 sA, u32 sB,
                                           const __half* A, const __half* B,
                                           int m0, int n0, int KA, int k0, int tid) {
#pragma unroll
    for (int l = 0; l < 4; l++) {
        int i = tid + l * 256;
        int r = i >> 3, c = i & 7;
        cp_async16(sA + sw128((u32)(r * 128 + c * 16)),
                   A + (size_t)(m0 + r) * KA + k0 + c * 8);
    }
#pragma unroll
    for (int l = 0; l < 4; l++) {
        int i = tid + l * 256;
        int r = i >> 3, c = i & 7;
        cp_async16(sB + sw128((u32)(r * 128 + c * 16)),
                   B + (size_t)(n0 + r) * KA + k0 + c * 8);
    }
}

__global__ void __launch_bounds__(256)
mma_gemm_kernel(const __half* __restrict__ A, const __half* __restrict__ B,
                const float* __restrict__ bias, int M, int KA, int mode) {
    extern __shared__ char smem[];
    const u32 sbase = smem_u32(smem);
    const int tid  = threadIdx.x;
    const int lane = tid & 31;
    const int warp = tid >> 5;
    const int m0 = blockIdx.y * 128;
    const int n0 = blockIdx.x * 128;
    const int wm = (warp & 3) * 32;
    const int wn = (warp >> 2) * 64;

    const u32 sA[2] = { sbase,         sbase + 32768 };
    const u32 sB[2] = { sbase + 16384, sbase + 49152 };

    float acc[2][8][4];
#pragma unroll
    for (int mt = 0; mt < 2; mt++)
#pragma unroll
        for (int j = 0; j < 8; j++)
#pragma unroll
            for (int q = 0; q < 4; q++) acc[mt][j][q] = 0.f;

    const int NT = KA >> 6;
    load_tiles(sA[0], sB[0], A, B, m0, n0, KA, 0, tid);
    CP_COMMIT();

    for (int t = 0; t < NT; t++) {
        if (t + 1 < NT) {
            load_tiles(sA[(t + 1) & 1], sB[(t + 1) & 1], A, B, m0, n0, KA, (t + 1) << 6, tid);
            CP_COMMIT();
            CP_WAIT(1);
        } else {
            CP_WAIT(0);
        }
        __syncthreads();

        const u32 a_base = sA[t & 1];
        const u32 b_base = sB[t & 1];
        const int ro = lane & 15;
        const int co = (lane >> 4) * 16;
#pragma unroll
        for (int ks = 0; ks < 4; ks++) {
            u32 a[2][4], b[4][4];
#pragma unroll
            for (int mt = 0; mt < 2; mt++)
                ldsm4(a[mt][0], a[mt][1], a[mt][2], a[mt][3],
                      a_base + sw128((u32)((wm + mt * 16 + ro) * 128 + ks * 32 + co)));
#pragma unroll
            for (int ng = 0; ng < 4; ng++)
                ldsm4(b[ng][0], b[ng][1], b[ng][2], b[ng][3],
                      b_base + sw128((u32)((wn + ng * 16 + ro) * 128 + ks * 32 + co)));
#pragma unroll
            for (int mt = 0; mt < 2; mt++)
#pragma unroll
                for (int j = 0; j < 8; j++)
                    mma16816(acc[mt][j], a[mt], b[j >> 1][j & 1], b[j >> 1][(j & 1) + 2]);
        }
        __syncthreads();
    }

    // ---------------- epilogue ----------------
    const int rbase = m0 + wm + (lane >> 2);
    const int cbase = n0 + wn + (lane & 3) * 2;

    float cs[8][2], cq[8][2];
    if (mode == 2) {
#pragma unroll
        for (int j = 0; j < 8; j++) { cs[j][0]=cs[j][1]=cq[j][0]=cq[j][1]=0.f; }
    }

#pragma unroll
    for (int mt = 0; mt < 2; mt++) {
#pragma unroll
        for (int half = 0; half < 2; half++) {
            const int row = rbase + mt * 16 + half * 8;
            if (row >= M) continue;
            if (mode == 1) {
                __half* ar = g_A2 + (size_t)row * KA2;
#pragma unroll
                for (int j = 0; j < 8; j++) {
                    const int col = cbase + j * 8;
                    float v0 = acc[mt][j][half * 2 + 0] + __ldg(bias + col);
                    float v1 = acc[mt][j][half * 2 + 1] + __ldg(bias + col + 1);
                    v0 = fmaxf(v0, 0.f); v1 = fmaxf(v1, 0.f);
                    __half h0 = __float2half_rn(v0);
                    __half h1 = __float2half_rn(v1);
                    u32 hw = (u32)__half_as_ushort(h0) | ((u32)__half_as_ushort(h1) << 16);
                    *(u32*)(ar + col) = hw;
                }
            } else {
                float* orow = g_h2 + (size_t)row * DIM;
#pragma unroll
                for (int j = 0; j < 8; j++) {
                    const int col = cbase + j * 8;
                    float2 v;
                    v.x = acc[mt][j][half * 2 + 0] + __ldg(bias + col);
                    v.y = acc[mt][j][half * 2 + 1] + __ldg(bias + col + 1);
                    *(float2*)(orow + col) = v;
                    cs[j][0] += v.x;  cs[j][1] += v.y;
                    cq[j][0] += v.x * v.x;  cq[j][1] += v.y * v.y;
                }
            }
        }
    }

    if (mode == 2) {
        // reduce across the 8 threads (lane bits 2,3,4) sharing each column
#pragma unroll
        for (int j = 0; j < 8; j++) {
#pragma unroll
            for (int c = 0; c < 2; c++) {
                float s = cs[j][c], q = cq[j][c];
#pragma unroll
                for (int o = 4; o < 32; o <<= 1) {
                    s += __shfl_xor_sync(0xffffffffu, s, o);
                    q += __shfl_xor_sync(0xffffffffu, q, o);
                }
                if ((lane >> 2) == 0) {
                    const int col = (cbase & 255) + j * 8 + c;
                    atomicAdd(&g_colsum[col], s);
                    atomicAdd(&g_colsq[col],  q);
                }
            }
        }
    }
}

// ---------------------------------------------------------------------------
// BatchNorm finalize + apply
// ---------------------------------------------------------------------------
__global__ void bn_finalize_kernel(float invN) {
    int tid = threadIdx.x;
    float m = g_colsum[tid] * invN;
    g_mean[tid] = m;
    g_istd[tid] = rsqrtf(g_colsq[tid] * invN - m * m + 1e-5f);
}
__global__ void bn_apply_kernel(const float* __restrict__ gamma,
                                const float* __restrict__ beta,
                                float* __restrict__ out, long long nq4) {
    long long t = (long long)blockIdx.x * blockDim.x + threadIdx.x;
    if (t >= nq4) return;
    int c4 = (int)(t & 63);
    float4 v  = ((const float4*)g_h2)[t];
    float4 m  = ((const float4*)g_mean)[c4];
    float4 is = ((const float4*)g_istd)[c4];
    float4 g  = ((const float4*)gamma)[c4];
    float4 b  = ((const float4*)beta)[c4];
    float4 o;
    o.x = (v.x - m.x) * is.x * g.x + b.x;
    o.y = (v.y - m.y) * is.y * g.y + b.y;
    o.z = (v.z - m.z) * is.z * g.z + b.z;
    o.w = (v.w - m.w) * is.w * g.w + b.w;
    ((float4*)out)[t] = o;
}

// ---------------------------------------------------------------------------
// launch
// ---------------------------------------------------------------------------
extern "C" void kernel_launch(void* const* d_in, const int* in_sizes, int n_in,
                              void* d_out, int out_size) {
    const float* x     = (const float*)d_in[0];
    const void*  src   = d_in[1];
    const void*  dst   = d_in[2];
    const float* eps   = (const float*)d_in[3];
    const float* W1    = (const float*)d_in[4];
    const float* b1    = (const float*)d_in[5];
    const float* W2    = (const float*)d_in[6];
    const float* b2    = (const float*)d_in[7];
    const float* gamma = (const float*)d_in[8];
    const float* beta  = (const float*)d_in[9];
    float* out = (float*)d_out;

    const long long n = (long long)in_sizes[0] / DIM;   // 100000
    const long long e = (long long)in_sizes[1];         // 1600000
    const int ni = (int)n;
    const int nb1024 = (ni + 1023) / 1024;

    __half *A1, *A2, *B1, *B2;
    cudaGetSymbolAddress((void**)&A1, g_A1);
    cudaGetSymbolAddress((void**)&A2, g_A2);
    cudaGetSymbolAddress((void**)&B1, g_B1);
    cudaGetSymbolAddress((void**)&B2, g_B2);

    cudaFuncSetAttribute(mma_gemm_kernel, cudaFuncAttributeMaxDynamicSharedMemorySize, SMEM_SZ);

    // 0) index dtype
    detect_idx_kernel<<<1, 1>>>((const int*)src);

    // 1) CSR build
    zero_kernel<<<(ni + 255) / 256, 256>>>(ni);
    hist_kernel<<<(int)((e + 255) / 256), 256>>>(dst, e);
    scan1_kernel<<<nb1024, 1024>>>(ni);
    scan2_kernel<<<1, 128>>>(nb1024);
    scan3_kernel<<<(ni + 255) / 256, 256>>>(ni);
    fill_kernel<<<(int)((e + 255) / 256), 256>>>(src, dst, e);

    // 2) fused gather + seed + fp16 split (writes g_A1 directly)
    gather_kernel<<<(ni + 3) / 4, 256>>>(x, eps, ni);

    // 3) weight conversions
    conv_W1_kernel<<<(DIM * DIM2 + 255) / 256, 256>>>(W1);
    conv_W2_kernel<<<(DIM2 * DIM + 255) / 256, 256>>>(W2);

    // 4) MLP on HMMA; GEMM2 fuses BN stats
    int mtiles = MPAD / 128;    // 782
    dim3 g1(DIM2 / 128, mtiles);
    mma_gemm_kernel<<<g1, 256, SMEM_SZ>>>(A1, B1, b1, ni, KA1, 1);
    dim3 g2(DIM / 128, mtiles);
    mma_gemm_kernel<<<g2, 256, SMEM_SZ>>>(A2, B2, b2, ni, KA2, 2);

    // 5) BatchNorm
    bn_finalize_kernel<<<1, 256>>>(1.0f / (float)n);
    long long nq4 = n * DIM / 4;
    bn_apply_kernel<<<(int)((nq4 + 255) / 256), 256>>>(gamma, beta, out, nq4);
}

// round 14
// speedup vs baseline: 4.8338x; 1.3629x over previous
#include <cuda_runtime.h>
#include <cuda_fp16.h>

// ---------------------------------------------------------------------------
// GIN layer: out = BN( relu( ((1+eps)x + scatter_sum(x[src]->dst)) @ W1 + b1 ) @ W2 + b2 )
// N=100000, D=256, E=1600000.
// x pre-converted to fp16; CSR counting-sort + 1-warp/node fp16 gather (fp32 acc);
// HMMA fp16 MLP (plain fp16 both GEMMs); BN stats fused into GEMM2 epilogue.
// ---------------------------------------------------------------------------

#define NNODE 100000
#define MPAD  100096          // 782 * 128
#define EMAX  1600000
#define DIM   256
#define DIM2  512
#define KA1   256             // GEMM1 K (plain fp16)
#define KA2   512             // GEMM2 K (plain fp16)

typedef unsigned int u32;

// ----------------------------- scratch (globals) ---------------------------
__device__ __align__(1024) float  g_h2 [(size_t)NNODE * DIM];
__device__ __align__(1024) __half g_x16[(size_t)NNODE * DIM];   // fp16 copy of x
__device__ __align__(1024) __half g_A1[(size_t)MPAD * KA1];     // agg, fp16 (pad rows unused outputs)
__device__ __align__(1024) __half g_A2[(size_t)MPAD * KA2];     // fp16 h1
__device__ __align__(1024) __half g_B1[(size_t)DIM2 * KA1];     // W1^T fp16
__device__ __align__(1024) __half g_B2[(size_t)DIM  * KA2];     // W2^T fp16
__device__ int   g_deg[NNODE];
__device__ int   g_off[NNODE];
__device__ int   g_cursor[NNODE];
__device__ int   g_csr[EMAX];
__device__ int   g_bsum[128];
__device__ int   g_boff[128];
__device__ float g_colsum[DIM];
__device__ float g_colsq[DIM];
__device__ float g_mean[DIM];
__device__ float g_istd[DIM];
__device__ int   g_idx64;

// ----------------------------- helpers -------------------------------------
__device__ __forceinline__ u32 smem_u32(const void* p) {
    u32 a;
    asm("{ .reg .u64 t; cvta.to.shared.u64 t, %1; cvt.u32.u64 %0, t; }" : "=r"(a) : "l"(p));
    return a;
}
__device__ __forceinline__ u32 sw128(u32 o) { return o ^ ((o >> 3) & 0x70); }

__device__ __forceinline__ void cp_async16(u32 saddr, const void* g) {
    asm volatile("cp.async.cg.shared.global [%0], [%1], 16;" :: "r"(saddr), "l"(g));
}
#define CP_COMMIT()  asm volatile("cp.async.commit_group;")
#define CP_WAIT(n)   asm volatile("cp.async.wait_group %0;" :: "n"(n) : "memory")

__device__ __forceinline__ void ldsm4(u32& r0, u32& r1, u32& r2, u32& r3, u32 addr) {
    asm volatile("ldmatrix.sync.aligned.m8n8.x4.shared.b16 {%0,%1,%2,%3}, [%4];"
                 : "=r"(r0), "=r"(r1), "=r"(r2), "=r"(r3) : "r"(addr));
}
__device__ __forceinline__ void mma16816(float* c, const u32* a, u32 b0, u32 b1) {
    asm volatile(
        "mma.sync.aligned.m16n8k16.row.col.f32.f16.f16.f32 "
        "{%0,%1,%2,%3}, {%4,%5,%6,%7}, {%8,%9}, {%0,%1,%2,%3};"
        : "+f"(c[0]), "+f"(c[1]), "+f"(c[2]), "+f"(c[3])
        : "r"(a[0]), "r"(a[1]), "r"(a[2]), "r"(a[3]), "r"(b0), "r"(b1));
}

__device__ __forceinline__ void acc_u4(float2* a, uint4 v) {
    float2 f0 = __half22float2(*(__half2*)&v.x);
    float2 f1 = __half22float2(*(__half2*)&v.y);
    float2 f2 = __half22float2(*(__half2*)&v.z);
    float2 f3 = __half22float2(*(__half2*)&v.w);
    a[0].x += f0.x; a[0].y += f0.y;
    a[1].x += f1.x; a[1].y += f1.y;
    a[2].x += f2.x; a[2].y += f2.y;
    a[3].x += f3.x; a[3].y += f3.y;
}

// ---------------------------------------------------------------------------
// index dtype detection
// ---------------------------------------------------------------------------
__global__ void detect_idx_kernel(const int* __restrict__ w) {
    int z = 1;
    for (int i = 1; i < 129; i += 2) if (w[i] != 0) { z = 0; break; }
    g_idx64 = z;
}
__device__ __forceinline__ int load_idx(const void* p, long long i) {
    if (g_idx64) return (int)((const long long*)p)[i];
    return ((const int*)p)[i];
}

// ---------------------------------------------------------------------------
// x -> fp16
// ---------------------------------------------------------------------------
__global__ void conv_x_kernel(const float* __restrict__ x, long long n8) {
    long long t = (long long)blockIdx.x * blockDim.x + threadIdx.x;
    if (t >= n8) return;
    float4 a = ((const float4*)x)[2 * t];
    float4 b = ((const float4*)x)[2 * t + 1];
    uint4 o;
    __half2 h;
    h = __floats2half2_rn(a.x, a.y); o.x = *(u32*)&h;
    h = __floats2half2_rn(a.z, a.w); o.y = *(u32*)&h;
    h = __floats2half2_rn(b.x, b.y); o.z = *(u32*)&h;
    h = __floats2half2_rn(b.z, b.w); o.w = *(u32*)&h;
    ((uint4*)g_x16)[t] = o;
}

// ---------------------------------------------------------------------------
// CSR build: zero -> histogram(dst) -> exclusive scan -> fill
// ---------------------------------------------------------------------------
__global__ void zero_kernel(int n) {
    int t = blockIdx.x * blockDim.x + threadIdx.x;
    if (t < n) g_deg[t] = 0;
    if (t < DIM) { g_colsum[t] = 0.f; g_colsq[t] = 0.f; }
}
__global__ void hist_kernel(const void* __restrict__ dst, long long ne) {
    long long e = (long long)blockIdx.x * blockDim.x + threadIdx.x;
    if (e >= ne) return;
    atomicAdd(&g_deg[load_idx(dst, e)], 1);
}
__global__ void scan1_kernel(int n) {
    __shared__ int sh[1024];
    int gid = blockIdx.x * 1024 + threadIdx.x;
    int v = (gid < n) ? g_deg[gid] : 0;
    sh[threadIdx.x] = v;
    __syncthreads();
#pragma unroll
    for (int off = 1; off < 1024; off <<= 1) {
        int t = (threadIdx.x >= off) ? sh[threadIdx.x - off] : 0;
        __syncthreads();
        sh[threadIdx.x] += t;
        __syncthreads();
    }
    if (gid < n) g_off[gid] = sh[threadIdx.x] - v;      // block-local exclusive
    if (threadIdx.x == 1023) g_bsum[blockIdx.x] = sh[1023];
}
__global__ void scan2_kernel(int nb) {
    __shared__ int sh[128];
    int v = (threadIdx.x < nb) ? g_bsum[threadIdx.x] : 0;
    sh[threadIdx.x] = v;
    __syncthreads();
#pragma unroll
    for (int off = 1; off < 128; off <<= 1) {
        int t = (threadIdx.x >= off) ? sh[threadIdx.x - off] : 0;
        __syncthreads();
        sh[threadIdx.x] += t;
        __syncthreads();
    }
    if (threadIdx.x < nb) g_boff[threadIdx.x] = sh[threadIdx.x] - v;
}
__global__ void scan3_kernel(int n) {
    int t = blockIdx.x * blockDim.x + threadIdx.x;
    if (t >= n) return;
    int o = g_off[t] + g_boff[t >> 10];
    g_off[t] = o;
    g_cursor[t] = o;
}
__global__ void fill_kernel(const void* __restrict__ src,
                            const void* __restrict__ dst, long long ne) {
    long long e = (long long)blockIdx.x * blockDim.x + threadIdx.x;
    if (e >= ne) return;
    int s = load_idx(src, e);
    int d = load_idx(dst, e);
    int pos = atomicAdd(&g_cursor[d], 1);
    g_csr[pos] = s;
}

// ---------------------------------------------------------------------------
// gather (fp16 in, fp32 acc): ONE warp per node; lane owns 8 columns (uint4).
// A1[node] = fp16( (1+eps)*x[node] + sum_{s in N(node)} x16[s] )
// ---------------------------------------------------------------------------
__global__ void __launch_bounds__(256)
gather_kernel(const float* __restrict__ eps, int n) {
    const int node = blockIdx.x * 8 + (threadIdx.x >> 5);
    if (node >= n) return;
    const int lane = threadIdx.x & 31;
    const int start = g_off[node];
    const int deg   = g_deg[node];
    const uint4* xb = (const uint4*)g_x16;   // 32 uint4 per 256-half row

    float2 a[4];
#pragma unroll
    for (int i = 0; i < 4; i++) a[i] = make_float2(0.f, 0.f);

    for (int base = 0; base < deg; base += 32) {
        const int cnt = min(32, deg - base);
        int sj = 0;
        if (lane < cnt) sj = g_csr[start + base + lane];
        int k = 0;
        for (; k + 1 < cnt; k += 2) {
            int s0 = __shfl_sync(0xffffffffu, sj, k);
            int s1 = __shfl_sync(0xffffffffu, sj, k + 1);
            uint4 v0 = __ldg(xb + (size_t)s0 * 32 + lane);
            uint4 v1 = __ldg(xb + (size_t)s1 * 32 + lane);
            acc_u4(a, v0);
            acc_u4(a, v1);
        }
        if (k < cnt) {
            int s0 = __shfl_sync(0xffffffffu, sj, k);
            uint4 v0 = __ldg(xb + (size_t)s0 * 32 + lane);
            acc_u4(a, v0);
        }
    }

    // self term: (1+eps) * x16[node]
    const float sc = 1.0f + eps[0];
    uint4 v = __ldg(xb + (size_t)node * 32 + lane);
    {
        float2 f0 = __half22float2(*(__half2*)&v.x);
        float2 f1 = __half22float2(*(__half2*)&v.y);
        float2 f2 = __half22float2(*(__half2*)&v.z);
        float2 f3 = __half22float2(*(__half2*)&v.w);
        a[0].x = fmaf(sc, f0.x, a[0].x); a[0].y = fmaf(sc, f0.y, a[0].y);
        a[1].x = fmaf(sc, f1.x, a[1].x); a[1].y = fmaf(sc, f1.y, a[1].y);
        a[2].x = fmaf(sc, f2.x, a[2].x); a[2].y = fmaf(sc, f2.y, a[2].y);
        a[3].x = fmaf(sc, f3.x, a[3].x); a[3].y = fmaf(sc, f3.y, a[3].y);
    }

    uint4 o;
    __half2 h;
    h = __floats2half2_rn(a[0].x, a[0].y); o.x = *(u32*)&h;
    h = __floats2half2_rn(a[1].x, a[1].y); o.y = *(u32*)&h;
    h = __floats2half2_rn(a[2].x, a[2].y); o.z = *(u32*)&h;
    h = __floats2half2_rn(a[3].x, a[3].y); o.w = *(u32*)&h;
    ((uint4*)(g_A1 + (size_t)node * KA1))[lane] = o;
}

// ---------------------------------------------------------------------------
// weight conversions
// ---------------------------------------------------------------------------
__global__ void conv_W1_kernel(const float* __restrict__ W1) {  // [256,512] -> g_B1 [512][256]
    int t = blockIdx.x * blockDim.x + threadIdx.x;
    if (t >= DIM * DIM2) return;
    int k = t >> 9, n = t & 511;
    g_B1[(size_t)n * KA1 + k] = __float2half_rn(W1[t]);
}
__global__ void conv_W2_kernel(const float* __restrict__ W2) {  // [512,256] -> g_B2 [256][512]
    int t = blockIdx.x * blockDim.x + threadIdx.x;
    if (t >= DIM2 * DIM) return;
    int k = t >> 8, n = t & 255;
    g_B2[(size_t)n * KA2 + k] = __float2half_rn(W2[t]);
}

// ---------------------------------------------------------------------------
// HMMA GEMM: 128x128 CTA tile, 8 warps (32x64), m16n8k16, cp.async dbuf, SW128.
// mode 1: relu(D + bias) -> plain fp16 -> g_A2
// mode 2: D + bias -> fp32 g_h2, plus fused BN column sum/sumsq atomics
// ---------------------------------------------------------------------------
#define SMEM_SZ 65536

__device__ __forceinline__ void load_tiles(u32 sA, u32 sB,
                                           const __half* A, const __half* B,
                                           int m0, int n0, int KA, int k0, int tid) {
#pragma unroll
    for (int l = 0; l < 4; l++) {
        int i = tid + l * 256;
        int r = i >> 3, c = i & 7;
        cp_async16(sA + sw128((u32)(r * 128 + c * 16)),
                   A + (size_t)(m0 + r) * KA + k0 + c * 8);
    }
#pragma unroll
    for (int l = 0; l < 4; l++) {
        int i = tid + l * 256;
        int r = i >> 3, c = i & 7;
        cp_async16(sB + sw128((u32)(r * 128 + c * 16)),
                   B + (size_t)(n0 + r) * KA + k0 + c * 8);
    }
}

__global__ void __launch_bounds__(256)
mma_gemm_kernel(const __half* __restrict__ A, const __half* __restrict__ B,
                const float* __restrict__ bias, int M, int KA, int mode) {
    extern __shared__ char smem[];
    const u32 sbase = smem_u32(smem);
    const int tid  = threadIdx.x;
    const int lane = tid & 31;
    const int warp = tid >> 5;
    const int m0 = blockIdx.y * 128;
    const int n0 = blockIdx.x * 128;
    const int wm = (warp & 3) * 32;
    const int wn = (warp >> 2) * 64;

    const u32 sA[2] = { sbase,         sbase + 32768 };
    const u32 sB[2] = { sbase + 16384, sbase + 49152 };

    float acc[2][8][4];
#pragma unroll
    for (int mt = 0; mt < 2; mt++)
#pragma unroll
        for (int j = 0; j < 8; j++)
#pragma unroll
            for (int q = 0; q < 4; q++) acc[mt][j][q] = 0.f;

    const int NT = KA >> 6;
    load_tiles(sA[0], sB[0], A, B, m0, n0, KA, 0, tid);
    CP_COMMIT();

    for (int t = 0; t < NT; t++) {
        if (t + 1 < NT) {
            load_tiles(sA[(t + 1) & 1], sB[(t + 1) & 1], A, B, m0, n0, KA, (t + 1) << 6, tid);
            CP_COMMIT();
            CP_WAIT(1);
        } else {
            CP_WAIT(0);
        }
        __syncthreads();

        const u32 a_base = sA[t & 1];
        const u32 b_base = sB[t & 1];
        const int ro = lane & 15;
        const int co = (lane >> 4) * 16;
#pragma unroll
        for (int ks = 0; ks < 4; ks++) {
            u32 a[2][4], b[4][4];
#pragma unroll
            for (int mt = 0; mt < 2; mt++)
                ldsm4(a[mt][0], a[mt][1], a[mt][2], a[mt][3],
                      a_base + sw128((u32)((wm + mt * 16 + ro) * 128 + ks * 32 + co)));
#pragma unroll
            for (int ng = 0; ng < 4; ng++)
                ldsm4(b[ng][0], b[ng][1], b[ng][2], b[ng][3],
                      b_base + sw128((u32)((wn + ng * 16 + ro) * 128 + ks * 32 + co)));
#pragma unroll
            for (int mt = 0; mt < 2; mt++)
#pragma unroll
                for (int j = 0; j < 8; j++)
                    mma16816(acc[mt][j], a[mt], b[j >> 1][j & 1], b[j >> 1][(j & 1) + 2]);
        }
        __syncthreads();
    }

    // ---------------- epilogue ----------------
    const int rbase = m0 + wm + (lane >> 2);
    const int cbase = n0 + wn + (lane & 3) * 2;

    float cs[8][2], cq[8][2];
    if (mode == 2) {
#pragma unroll
        for (int j = 0; j < 8; j++) { cs[j][0]=cs[j][1]=cq[j][0]=cq[j][1]=0.f; }
    }

#pragma unroll
    for (int mt = 0; mt < 2; mt++) {
#pragma unroll
        for (int half = 0; half < 2; half++) {
            const int row = rbase + mt * 16 + half * 8;
            if (row >= M) continue;
            if (mode == 1) {
                __half* ar = g_A2 + (size_t)row * KA2;
#pragma unroll
                for (int j = 0; j < 8; j++) {
                    const int col = cbase + j * 8;
                    float v0 = acc[mt][j][half * 2 + 0] + __ldg(bias + col);
                    float v1 = acc[mt][j][half * 2 + 1] + __ldg(bias + col + 1);
                    v0 = fmaxf(v0, 0.f); v1 = fmaxf(v1, 0.f);
                    __half2 h = __floats2half2_rn(v0, v1);
                    *(u32*)(ar + col) = *(u32*)&h;
                }
            } else {
                float* orow = g_h2 + (size_t)row * DIM;
#pragma unroll
                for (int j = 0; j < 8; j++) {
                    const int col = cbase + j * 8;
                    float2 v;
                    v.x = acc[mt][j][half * 2 + 0] + __ldg(bias + col);
                    v.y = acc[mt][j][half * 2 + 1] + __ldg(bias + col + 1);
                    *(float2*)(orow + col) = v;
                    cs[j][0] += v.x;  cs[j][1] += v.y;
                    cq[j][0] += v.x * v.x;  cq[j][1] += v.y * v.y;
                }
            }
        }
    }

    if (mode == 2) {
        // reduce across the 8 threads (lane bits 2,3,4) sharing each column
#pragma unroll
        for (int j = 0; j < 8; j++) {
#pragma unroll
            for (int c = 0; c < 2; c++) {
                float s = cs[j][c], q = cq[j][c];
#pragma unroll
                for (int o = 4; o < 32; o <<= 1) {
                    s += __shfl_xor_sync(0xffffffffu, s, o);
                    q += __shfl_xor_sync(0xffffffffu, q, o);
                }
                if ((lane >> 2) == 0) {
                    const int col = (cbase & 255) + j * 8 + c;
                    atomicAdd(&g_colsum[col], s);
                    atomicAdd(&g_colsq[col],  q);
                }
            }
        }
    }
}

// ---------------------------------------------------------------------------
// BatchNorm finalize + apply
// ---------------------------------------------------------------------------
__global__ void bn_finalize_kernel(float invN) {
    int tid = threadIdx.x;
    float m = g_colsum[tid] * invN;
    g_mean[tid] = m;
    g_istd[tid] = rsqrtf(g_colsq[tid] * invN - m * m + 1e-5f);
}
__global__ void bn_apply_kernel(const float* __restrict__ gamma,
                                const float* __restrict__ beta,
                                float* __restrict__ out, long long nq4) {
    long long t = (long long)blockIdx.x * blockDim.x + threadIdx.x;
    if (t >= nq4) return;
    int c4 = (int)(t & 63);
    float4 v  = ((const float4*)g_h2)[t];
    float4 m  = ((const float4*)g_mean)[c4];
    float4 is = ((const float4*)g_istd)[c4];
    float4 g  = ((const float4*)gamma)[c4];
    float4 b  = ((const float4*)beta)[c4];
    float4 o;
    o.x = (v.x - m.x) * is.x * g.x + b.x;
    o.y = (v.y - m.y) * is.y * g.y + b.y;
    o.z = (v.z - m.z) * is.z * g.z + b.z;
    o.w = (v.w - m.w) * is.w * g.w + b.w;
    ((float4*)out)[t] = o;
}

// ---------------------------------------------------------------------------
// launch
// ---------------------------------------------------------------------------
extern "C" void kernel_launch(void* const* d_in, const int* in_sizes, int n_in,
                              void* d_out, int out_size) {
    const float* x     = (const float*)d_in[0];
    const void*  src   = d_in[1];
    const void*  dst   = d_in[2];
    const float* eps   = (const float*)d_in[3];
    const float* W1    = (const float*)d_in[4];
    const float* b1    = (const float*)d_in[5];
    const float* W2    = (const float*)d_in[6];
    const float* b2    = (const float*)d_in[7];
    const float* gamma = (const float*)d_in[8];
    const float* beta  = (const float*)d_in[9];
    float* out = (float*)d_out;

    const long long n = (long long)in_sizes[0] / DIM;   // 100000
    const long long e = (long long)in_sizes[1];         // 1600000
    const int ni = (int)n;
    const int nb1024 = (ni + 1023) / 1024;

    __half *A1, *A2, *B1, *B2;
    cudaGetSymbolAddress((void**)&A1, g_A1);
    cudaGetSymbolAddress((void**)&A2, g_A2);
    cudaGetSymbolAddress((void**)&B1, g_B1);
    cudaGetSymbolAddress((void**)&B2, g_B2);

    cudaFuncSetAttribute(mma_gemm_kernel, cudaFuncAttributeMaxDynamicSharedMemorySize, SMEM_SZ);

    // 0) index dtype + x -> fp16
    detect_idx_kernel<<<1, 1>>>((const int*)src);
    long long n8 = n * DIM / 8;
    conv_x_kernel<<<(int)((n8 + 255) / 256), 256>>>(x, n8);

    // 1) CSR build
    zero_kernel<<<(ni + 255) / 256, 256>>>(ni);
    hist_kernel<<<(int)((e + 255) / 256), 256>>>(dst, e);
    scan1_kernel<<<nb1024, 1024>>>(ni);
    scan2_kernel<<<1, 128>>>(nb1024);
    scan3_kernel<<<(ni + 255) / 256, 256>>>(ni);
    fill_kernel<<<(int)((e + 255) / 256), 256>>>(src, dst, e);

    // 2) fused gather + seed (fp16 in, fp32 acc, fp16 out -> g_A1)
    gather_kernel<<<(ni + 7) / 8, 256>>>(eps, ni);

    // 3) weight conversions
    conv_W1_kernel<<<(DIM * DIM2 + 255) / 256, 256>>>(W1);
    conv_W2_kernel<<<(DIM2 * DIM + 255) / 256, 256>>>(W2);

    // 4) MLP on HMMA; GEMM2 fuses BN stats
    int mtiles = MPAD / 128;    // 782
    dim3 g1(DIM2 / 128, mtiles);
    mma_gemm_kernel<<<g1, 256, SMEM_SZ>>>(A1, B1, b1, ni, KA1, 1);
    dim3 g2(DIM / 128, mtiles);
    mma_gemm_kernel<<<g2, 256, SMEM_SZ>>>(A2, B2, b2, ni, KA2, 2);

    // 5) BatchNorm
    bn_finalize_kernel<<<1, 256>>>(1.0f / (float)n);
    long long nq4 = n * DIM / 4;
    bn_apply_kernel<<<(int)((nq4 + 255) / 256), 256>>>(gamma, beta, out, nq4);
}

// round 15
// speedup vs baseline: 4.9321x; 1.0203x over previous
#include <cuda_runtime.h>
#include <cuda_fp16.h>

// ---------------------------------------------------------------------------
// GIN layer: out = BN( relu( ((1+eps)x + scatter_sum(x[src]->dst)) @ W1 + b1 ) @ W2 + b2 )
// N=100000, D=256, E=1600000.
// x pre-converted to fp16; CSR counting-sort + 1-warp/node fp16 gather (fp32 acc);
// HMMA fp16 MLP; BN stats fused into GEMM2 epilogue; compacted 9-launch DAG.
// ---------------------------------------------------------------------------

#define NNODE 100000
#define MPAD  100096          // 782 * 128
#define EMAX  1600000
#define DIM   256
#define DIM2  512
#define KA1   256             // GEMM1 K (plain fp16)
#define KA2   512             // GEMM2 K (plain fp16)

typedef unsigned int u32;

// ----------------------------- scratch (globals) ---------------------------
__device__ __align__(1024) float  g_h2 [(size_t)NNODE * DIM];
__device__ __align__(1024) __half g_x16[(size_t)NNODE * DIM];   // fp16 copy of x
__device__ __align__(1024) __half g_A1[(size_t)MPAD * KA1];     // agg, fp16
__device__ __align__(1024) __half g_A2[(size_t)MPAD * KA2];     // fp16 h1
__device__ __align__(1024) __half g_B1[(size_t)DIM2 * KA1];     // W1^T fp16
__device__ __align__(1024) __half g_B2[(size_t)DIM  * KA2];     // W2^T fp16
__device__ int   g_deg[NNODE];
__device__ int   g_off[NNODE];
__device__ int   g_cursor[NNODE];
__device__ int   g_csr[EMAX];
__device__ int   g_bsum[128];
__device__ float g_colsum[DIM];
__device__ float g_colsq[DIM];
__device__ int   g_idx64;

// ----------------------------- helpers -------------------------------------
__device__ __forceinline__ u32 smem_u32(const void* p) {
    u32 a;
    asm("{ .reg .u64 t; cvta.to.shared.u64 t, %1; cvt.u32.u64 %0, t; }" : "=r"(a) : "l"(p));
    return a;
}
__device__ __forceinline__ u32 sw128(u32 o) { return o ^ ((o >> 3) & 0x70); }

__device__ __forceinline__ void cp_async16(u32 saddr, const void* g) {
    asm volatile("cp.async.cg.shared.global [%0], [%1], 16;" :: "r"(saddr), "l"(g));
}
#define CP_COMMIT()  asm volatile("cp.async.commit_group;")
#define CP_WAIT(n)   asm volatile("cp.async.wait_group %0;" :: "n"(n) : "memory")

__device__ __forceinline__ void ldsm4(u32& r0, u32& r1, u32& r2, u32& r3, u32 addr) {
    asm volatile("ldmatrix.sync.aligned.m8n8.x4.shared.b16 {%0,%1,%2,%3}, [%4];"
                 : "=r"(r0), "=r"(r1), "=r"(r2), "=r"(r3) : "r"(addr));
}
__device__ __forceinline__ void mma16816(float* c, const u32* a, u32 b0, u32 b1) {
    asm volatile(
        "mma.sync.aligned.m16n8k16.row.col.f32.f16.f16.f32 "
        "{%0,%1,%2,%3}, {%4,%5,%6,%7}, {%8,%9}, {%0,%1,%2,%3};"
        : "+f"(c[0]), "+f"(c[1]), "+f"(c[2]), "+f"(c[3])
        : "r"(a[0]), "r"(a[1]), "r"(a[2]), "r"(a[3]), "r"(b0), "r"(b1));
}

__device__ __forceinline__ void acc_u4(float2* a, uint4 v) {
    float2 f0 = __half22float2(*(__half2*)&v.x);
    float2 f1 = __half22float2(*(__half2*)&v.y);
    float2 f2 = __half22float2(*(__half2*)&v.z);
    float2 f3 = __half22float2(*(__half2*)&v.w);
    a[0].x += f0.x; a[0].y += f0.y;
    a[1].x += f1.x; a[1].y += f1.y;
    a[2].x += f2.x; a[2].y += f2.y;
    a[3].x += f3.x; a[3].y += f3.y;
}

__device__ __forceinline__ int load_idx(const void* p, long long i) {
    if (g_idx64) return (int)((const long long*)p)[i];
    return ((const int*)p)[i];
}

// ---------------------------------------------------------------------------
// Kernel 1: zero deg/colsum/colsq + index-dtype detection
// ---------------------------------------------------------------------------
__global__ void zero_detect_kernel(const int* __restrict__ srcw, int n) {
    int t = blockIdx.x * blockDim.x + threadIdx.x;
    if (t < n) g_deg[t] = 0;
    if (t < DIM) { g_colsum[t] = 0.f; g_colsq[t] = 0.f; }
    if (t == 0) {
        int z = 1;
        for (int i = 1; i < 129; i += 2) if (srcw[i] != 0) { z = 0; break; }
        g_idx64 = z;
    }
}

// ---------------------------------------------------------------------------
// Kernel 2 (partitioned grid): conv_x || hist || conv_W1 || conv_W2
//   blocks [0, NB_CX)                : x -> fp16 (uint4 per thread)
//   blocks [NB_CX, +NB_H)            : dst histogram, 4 edges/thread
//   blocks [.., +NB_W1)              : W1 -> g_B1 (transposed fp16)
//   blocks [.., +NB_W2)              : W2 -> g_B2
// ---------------------------------------------------------------------------
#define NB_CX 12500                  // (N*DIM/8) / 256
#define NB_H  1563                   // ceil(E / 1024)
#define NB_W1 512                    // (256*512)/256
#define NB_W2 512

__global__ void prep_kernel(const float* __restrict__ x,
                            const void* __restrict__ dst,
                            const float* __restrict__ W1,
                            const float* __restrict__ W2,
                            long long n8, long long ne) {
    const int b = blockIdx.x;
    if (b < NB_CX) {
        long long t = (long long)b * 256 + threadIdx.x;
        if (t >= n8) return;
        float4 a = ((const float4*)x)[2 * t];
        float4 c = ((const float4*)x)[2 * t + 1];
        uint4 o; __half2 h;
        h = __floats2half2_rn(a.x, a.y); o.x = *(u32*)&h;
        h = __floats2half2_rn(a.z, a.w); o.y = *(u32*)&h;
        h = __floats2half2_rn(c.x, c.y); o.z = *(u32*)&h;
        h = __floats2half2_rn(c.z, c.w); o.w = *(u32*)&h;
        ((uint4*)g_x16)[t] = o;
    } else if (b < NB_CX + NB_H) {
        long long base = ((long long)(b - NB_CX) * 256 + threadIdx.x) * 4;
#pragma unroll
        for (int i = 0; i < 4; i++) {
            long long e = base + i;
            if (e < ne) atomicAdd(&g_deg[load_idx(dst, e)], 1);
        }
    } else if (b < NB_CX + NB_H + NB_W1) {
        int t = (b - NB_CX - NB_H) * 256 + threadIdx.x;
        int k = t >> 9, n = t & 511;
        g_B1[(size_t)n * KA1 + k] = __float2half_rn(W1[t]);
    } else {
        int t = (b - NB_CX - NB_H - NB_W1) * 256 + threadIdx.x;
        int k = t >> 8, n = t & 255;
        g_B2[(size_t)n * KA2 + k] = __float2half_rn(W2[t]);
    }
}

// ---------------------------------------------------------------------------
// Kernel 3: per-1024-block exclusive scan of degrees
// ---------------------------------------------------------------------------
__global__ void scan1_kernel(int n) {
    __shared__ int sh[1024];
    int gid = blockIdx.x * 1024 + threadIdx.x;
    int v = (gid < n) ? g_deg[gid] : 0;
    sh[threadIdx.x] = v;
    __syncthreads();
#pragma unroll
    for (int off = 1; off < 1024; off <<= 1) {
        int t = (threadIdx.x >= off) ? sh[threadIdx.x - off] : 0;
        __syncthreads();
        sh[threadIdx.x] += t;
        __syncthreads();
    }
    if (gid < n) g_off[gid] = sh[threadIdx.x] - v;      // block-local exclusive
    if (threadIdx.x == 1023) g_bsum[blockIdx.x] = sh[1023];
}

// ---------------------------------------------------------------------------
// Kernel 4: fused block-sum scan (redundant per block) + offset/cursor write
// ---------------------------------------------------------------------------
__global__ void scan23_kernel(int n, int nb) {
    __shared__ int sb[128];
    if (threadIdx.x < 128) sb[threadIdx.x] = (threadIdx.x < nb) ? g_bsum[threadIdx.x] : 0;
    __syncthreads();
    if (threadIdx.x == 0) {
        int acc = 0;
        for (int i = 0; i < nb; i++) { int v = sb[i]; sb[i] = acc; acc += v; }
    }
    __syncthreads();
    int gid = blockIdx.x * 1024 + threadIdx.x;
    if (gid < n) {
        int o = g_off[gid] + sb[blockIdx.x];
        g_off[gid] = o;
        g_cursor[gid] = o;
    }
}

// ---------------------------------------------------------------------------
// Kernel 5: CSR fill
// ---------------------------------------------------------------------------
__global__ void fill_kernel(const void* __restrict__ src,
                            const void* __restrict__ dst, long long ne) {
    long long e = (long long)blockIdx.x * blockDim.x + threadIdx.x;
    if (e >= ne) return;
    int s = load_idx(src, e);
    int d = load_idx(dst, e);
    int pos = atomicAdd(&g_cursor[d], 1);
    g_csr[pos] = s;
}

// ---------------------------------------------------------------------------
// Kernel 6: gather (fp16 in, fp32 acc): one warp per node, 8 cols/lane.
// A1[node] = fp16( (1+eps)*x16[node] + sum_{s in N(node)} x16[s] )
// ---------------------------------------------------------------------------
__global__ void __launch_bounds__(256)
gather_kernel(const float* __restrict__ eps, int n) {
    const int node = blockIdx.x * 8 + (threadIdx.x >> 5);
    if (node >= n) return;
    const int lane = threadIdx.x & 31;
    const int start = g_off[node];
    const int deg   = g_deg[node];
    const uint4* xb = (const uint4*)g_x16;   // 32 uint4 per 256-half row

    float2 a[4];
#pragma unroll
    for (int i = 0; i < 4; i++) a[i] = make_float2(0.f, 0.f);

    for (int base = 0; base < deg; base += 32) {
        const int cnt = min(32, deg - base);
        int sj = 0;
        if (lane < cnt) sj = g_csr[start + base + lane];
        int k = 0;
        for (; k + 1 < cnt; k += 2) {
            int s0 = __shfl_sync(0xffffffffu, sj, k);
            int s1 = __shfl_sync(0xffffffffu, sj, k + 1);
            uint4 v0 = __ldg(xb + (size_t)s0 * 32 + lane);
            uint4 v1 = __ldg(xb + (size_t)s1 * 32 + lane);
            acc_u4(a, v0);
            acc_u4(a, v1);
        }
        if (k < cnt) {
            int s0 = __shfl_sync(0xffffffffu, sj, k);
            uint4 v0 = __ldg(xb + (size_t)s0 * 32 + lane);
            acc_u4(a, v0);
        }
    }

    const float sc = 1.0f + eps[0];
    uint4 v = __ldg(xb + (size_t)node * 32 + lane);
    {
        float2 f0 = __half22float2(*(__half2*)&v.x);
        float2 f1 = __half22float2(*(__half2*)&v.y);
        float2 f2 = __half22float2(*(__half2*)&v.z);
        float2 f3 = __half22float2(*(__half2*)&v.w);
        a[0].x = fmaf(sc, f0.x, a[0].x); a[0].y = fmaf(sc, f0.y, a[0].y);
        a[1].x = fmaf(sc, f1.x, a[1].x); a[1].y = fmaf(sc, f1.y, a[1].y);
        a[2].x = fmaf(sc, f2.x, a[2].x); a[2].y = fmaf(sc, f2.y, a[2].y);
        a[3].x = fmaf(sc, f3.x, a[3].x); a[3].y = fmaf(sc, f3.y, a[3].y);
    }

    uint4 o; __half2 h;
    h = __floats2half2_rn(a[0].x, a[0].y); o.x = *(u32*)&h;
    h = __floats2half2_rn(a[1].x, a[1].y); o.y = *(u32*)&h;
    h = __floats2half2_rn(a[2].x, a[2].y); o.z = *(u32*)&h;
    h = __floats2half2_rn(a[3].x, a[3].y); o.w = *(u32*)&h;
    ((uint4*)(g_A1 + (size_t)node * KA1))[lane] = o;
}

// ---------------------------------------------------------------------------
// Kernels 7/8: HMMA GEMM, 128x128 CTA tile, 8 warps, m16n8k16, dbuf, SW128.
// mode 1: relu(D + bias) -> fp16 g_A2 ; mode 2: D + bias -> fp32 g_h2 + BN stats
// ---------------------------------------------------------------------------
#define SMEM_SZ 65536

__device__ __forceinline__ void load_tiles(u32 sA, u32 sB,
                                           const __half* A, const __half* B,
                                           int m0, int n0, int KA, int k0, int tid) {
#pragma unroll
    for (int l = 0; l < 4; l++) {
        int i = tid + l * 256;
        int r = i >> 3, c = i & 7;
        cp_async16(sA + sw128((u32)(r * 128 + c * 16)),
                   A + (size_t)(m0 + r) * KA + k0 + c * 8);
    }
#pragma unroll
    for (int l = 0; l < 4; l++) {
        int i = tid + l * 256;
        int r = i >> 3, c = i & 7;
        cp_async16(sB + sw128((u32)(r * 128 + c * 16)),
                   B + (size_t)(n0 + r) * KA + k0 + c * 8);
    }
}

__global__ void __launch_bounds__(256)
mma_gemm_kernel(const __half* __restrict__ A, const __half* __restrict__ B,
                const float* __restrict__ bias, int M, int KA, int mode) {
    extern __shared__ char smem[];
    const u32 sbase = smem_u32(smem);
    const int tid  = threadIdx.x;
    const int lane = tid & 31;
    const int warp = tid >> 5;
    const int m0 = blockIdx.y * 128;
    const int n0 = blockIdx.x * 128;
    const int wm = (warp & 3) * 32;
    const int wn = (warp >> 2) * 64;

    const u32 sA[2] = { sbase,         sbase + 32768 };
    const u32 sB[2] = { sbase + 16384, sbase + 49152 };

    float acc[2][8][4];
#pragma unroll
    for (int mt = 0; mt < 2; mt++)
#pragma unroll
        for (int j = 0; j < 8; j++)
#pragma unroll
            for (int q = 0; q < 4; q++) acc[mt][j][q] = 0.f;

    const int NT = KA >> 6;
    load_tiles(sA[0], sB[0], A, B, m0, n0, KA, 0, tid);
    CP_COMMIT();

    for (int t = 0; t < NT; t++) {
        if (t + 1 < NT) {
            load_tiles(sA[(t + 1) & 1], sB[(t + 1) & 1], A, B, m0, n0, KA, (t + 1) << 6, tid);
            CP_COMMIT();
            CP_WAIT(1);
        } else {
            CP_WAIT(0);
        }
        __syncthreads();

        const u32 a_base = sA[t & 1];
        const u32 b_base = sB[t & 1];
        const int ro = lane & 15;
        const int co = (lane >> 4) * 16;
#pragma unroll
        for (int ks = 0; ks < 4; ks++) {
            u32 a[2][4], b[4][4];
#pragma unroll
            for (int mt = 0; mt < 2; mt++)
                ldsm4(a[mt][0], a[mt][1], a[mt][2], a[mt][3],
                      a_base + sw128((u32)((wm + mt * 16 + ro) * 128 + ks * 32 + co)));
#pragma unroll
            for (int ng = 0; ng < 4; ng++)
                ldsm4(b[ng][0], b[ng][1], b[ng][2], b[ng][3],
                      b_base + sw128((u32)((wn + ng * 16 + ro) * 128 + ks * 32 + co)));
#pragma unroll
            for (int mt = 0; mt < 2; mt++)
#pragma unroll
                for (int j = 0; j < 8; j++)
                    mma16816(acc[mt][j], a[mt], b[j >> 1][j & 1], b[j >> 1][(j & 1) + 2]);
        }
        __syncthreads();
    }

    // ---------------- epilogue ----------------
    const int rbase = m0 + wm + (lane >> 2);
    const int cbase = n0 + wn + (lane & 3) * 2;

    float cs[8][2], cq[8][2];
    if (mode == 2) {
#pragma unroll
        for (int j = 0; j < 8; j++) { cs[j][0]=cs[j][1]=cq[j][0]=cq[j][1]=0.f; }
    }

#pragma unroll
    for (int mt = 0; mt < 2; mt++) {
#pragma unroll
        for (int half = 0; half < 2; half++) {
            const int row = rbase + mt * 16 + half * 8;
            if (row >= M) continue;
            if (mode == 1) {
                __half* ar = g_A2 + (size_t)row * KA2;
#pragma unroll
                for (int j = 0; j < 8; j++) {
                    const int col = cbase + j * 8;
                    float v0 = acc[mt][j][half * 2 + 0] + __ldg(bias + col);
                    float v1 = acc[mt][j][half * 2 + 1] + __ldg(bias + col + 1);
                    v0 = fmaxf(v0, 0.f); v1 = fmaxf(v1, 0.f);
                    __half2 h = __floats2half2_rn(v0, v1);
                    *(u32*)(ar + col) = *(u32*)&h;
                }
            } else {
                float* orow = g_h2 + (size_t)row * DIM;
#pragma unroll
                for (int j = 0; j < 8; j++) {
                    const int col = cbase + j * 8;
                    float2 v;
                    v.x = acc[mt][j][half * 2 + 0] + __ldg(bias + col);
                    v.y = acc[mt][j][half * 2 + 1] + __ldg(bias + col + 1);
                    *(float2*)(orow + col) = v;
                    cs[j][0] += v.x;  cs[j][1] += v.y;
                    cq[j][0] += v.x * v.x;  cq[j][1] += v.y * v.y;
                }
            }
        }
    }

    if (mode == 2) {
#pragma unroll
        for (int j = 0; j < 8; j++) {
#pragma unroll
            for (int c = 0; c < 2; c++) {
                float s = cs[j][c], q = cq[j][c];
#pragma unroll
                for (int o = 4; o < 32; o <<= 1) {
                    s += __shfl_xor_sync(0xffffffffu, s, o);
                    q += __shfl_xor_sync(0xffffffffu, q, o);
                }
                if ((lane >> 2) == 0) {
                    const int col = (cbase & 255) + j * 8 + c;
                    atomicAdd(&g_colsum[col], s);
                    atomicAdd(&g_colsq[col],  q);
                }
            }
        }
    }
}

// ---------------------------------------------------------------------------
// Kernel 9: BN finalize (per-block, from colsum/colsq) + apply
// ---------------------------------------------------------------------------
__global__ void __launch_bounds__(256)
bn_apply_kernel(const float* __restrict__ gamma,
                const float* __restrict__ beta,
                float* __restrict__ out, long long nq4, float invN) {
    __shared__ float s_scale[DIM], s_shift[DIM];
    const int tid = threadIdx.x;
    {
        float m  = g_colsum[tid] * invN;
        float is = rsqrtf(g_colsq[tid] * invN - m * m + 1e-5f);
        float sc = is * gamma[tid];
        s_scale[tid] = sc;
        s_shift[tid] = beta[tid] - m * sc;
    }
    __syncthreads();

    for (long long t = (long long)blockIdx.x * blockDim.x + tid; t < nq4;
         t += (long long)gridDim.x * blockDim.x) {
        int c4 = (int)(t & 63);
        float4 v  = ((const float4*)g_h2)[t];
        float4 sc = *(float4*)&s_scale[c4 * 4];
        float4 sh = *(float4*)&s_shift[c4 * 4];
        float4 o;
        o.x = fmaf(v.x, sc.x, sh.x);
        o.y = fmaf(v.y, sc.y, sh.y);
        o.z = fmaf(v.z, sc.z, sh.z);
        o.w = fmaf(v.w, sc.w, sh.w);
        ((float4*)out)[t] = o;
    }
}

// ---------------------------------------------------------------------------
// launch
// ---------------------------------------------------------------------------
extern "C" void kernel_launch(void* const* d_in, const int* in_sizes, int n_in,
                              void* d_out, int out_size) {
    const float* x     = (const float*)d_in[0];
    const void*  src   = d_in[1];
    const void*  dst   = d_in[2];
    const float* eps   = (const float*)d_in[3];
    const float* W1    = (const float*)d_in[4];
    const float* b1    = (const float*)d_in[5];
    const float* W2    = (const float*)d_in[6];
    const float* b2    = (const float*)d_in[7];
    const float* gamma = (const float*)d_in[8];
    const float* beta  = (const float*)d_in[9];
    float* out = (float*)d_out;

    const long long n = (long long)in_sizes[0] / DIM;   // 100000
    const long long e = (long long)in_sizes[1];         // 1600000
    const int ni = (int)n;
    const int nb1024 = (ni + 1023) / 1024;

    __half *A1, *A2, *B1, *B2;
    cudaGetSymbolAddress((void**)&A1, g_A1);
    cudaGetSymbolAddress((void**)&A2, g_A2);
    cudaGetSymbolAddress((void**)&B1, g_B1);
    cudaGetSymbolAddress((void**)&B2, g_B2);

    cudaFuncSetAttribute(mma_gemm_kernel, cudaFuncAttributeMaxDynamicSharedMemorySize, SMEM_SZ);

    // 1) zero + index-dtype detect
    zero_detect_kernel<<<(ni + 255) / 256, 256>>>((const int*)src, ni);

    // 2) conv_x || hist || conv_W1 || conv_W2 (partitioned grid)
    long long n8 = n * DIM / 8;
    prep_kernel<<<NB_CX + NB_H + NB_W1 + NB_W2, 256>>>(x, dst, W1, W2, n8, e);

    // 3-5) CSR build
    scan1_kernel<<<nb1024, 1024>>>(ni);
    scan23_kernel<<<nb1024, 1024>>>(ni, nb1024);
    fill_kernel<<<(int)((e + 255) / 256), 256>>>(src, dst, e);

    // 6) gather + seed (fp16 in, fp32 acc, fp16 out -> g_A1)
    gather_kernel<<<(ni + 7) / 8, 256>>>(eps, ni);

    // 7-8) MLP on HMMA; GEMM2 fuses BN stats
    int mtiles = MPAD / 128;    // 782
    dim3 g1(DIM2 / 128, mtiles);
    mma_gemm_kernel<<<g1, 256, SMEM_SZ>>>(A1, B1, b1, ni, KA1, 1);
    dim3 g2(DIM / 128, mtiles);
    mma_gemm_kernel<<<g2, 256, SMEM_SZ>>>(A2, B2, b2, ni, KA2, 2);

    // 9) BN finalize + apply
    long long nq4 = n * DIM / 4;
    bn_apply_kernel<<<1184, 256>>>(gamma, beta, out, nq4, 1.0f / (float)n);
}